// round 1
// baseline (speedup 1.0000x reference)
#include <cuda_runtime.h>

// Problem dims
#define B_  32
#define H_  56
#define W_  56
#define HW  3136          // 56*56
#define C_  256
#define F_  256
#define KK  2304          // 3*3*256
#define NK  4
#define PER_B (KK*F_)     // 589824 floats per sample effective kernel

// ---- scratch (device globals: allocation-guard safe) ----
__device__ float g_part[B_ * 16 * C_];
__device__ float g_pooled[B_ * C_];
__device__ float g_attn[B_ * NK];
__device__ float g_weff[(size_t)B_ * PER_B];   // 302 MB
__device__ float g_beff[B_ * F_];

// ============ 1) Global average pool (2-stage, deterministic) ============
__global__ void gap_partial_kernel(const float* __restrict__ x) {
    int b = blockIdx.x, chunk = blockIdx.y, c = threadIdx.x;   // 256 threads
    const float* xb = x + (size_t)b * HW * C_;
    float s = 0.f;
    int p0 = chunk * 196;
    #pragma unroll 4
    for (int p = p0; p < p0 + 196; ++p) s += xb[(size_t)p * C_ + c];
    g_part[(b * 16 + chunk) * C_ + c] = s;
}

__global__ void gap_final_kernel() {
    int b = blockIdx.x, c = threadIdx.x;
    float s = 0.f;
    #pragma unroll
    for (int ch = 0; ch < 16; ++ch) s += g_part[(b * 16 + ch) * C_ + c];
    g_pooled[b * C_ + c] = s * (1.0f / 3136.0f);
}

// ============ 2) Router MLP + softmax(logits/30) ============
__global__ void attn_kernel(const float* __restrict__ w1, const float* __restrict__ b1,
                            const float* __restrict__ w2, const float* __restrict__ b2) {
    int b = blockIdx.x, j = threadIdx.x;   // 64 threads
    __shared__ float sp[C_];
    __shared__ float sh[64];
    __shared__ float sl[NK];
    for (int c = j; c < C_; c += 64) sp[c] = g_pooled[b * C_ + c];
    __syncthreads();
    float acc = b1[j];
    #pragma unroll 4
    for (int c = 0; c < C_; ++c) acc += sp[c] * w1[c * 64 + j];
    sh[j] = fmaxf(acc, 0.f);
    __syncthreads();
    if (j < NK) {
        float lg = b2[j];
        #pragma unroll
        for (int i = 0; i < 64; ++i) lg += sh[i] * w2[i * NK + j];
        sl[j] = lg * (1.0f / 30.0f);
    }
    __syncthreads();
    if (j == 0) {
        float mx = fmaxf(fmaxf(sl[0], sl[1]), fmaxf(sl[2], sl[3]));
        float e0 = expf(sl[0] - mx), e1 = expf(sl[1] - mx);
        float e2 = expf(sl[2] - mx), e3 = expf(sl[3] - mx);
        float inv = 1.0f / (e0 + e1 + e2 + e3);
        g_attn[b * NK + 0] = e0 * inv;
        g_attn[b * NK + 1] = e1 * inv;
        g_attn[b * NK + 2] = e2 * inv;
        g_attn[b * NK + 3] = e3 * inv;
    }
}

// ============ 3) Per-sample effective weights & bias ============
// W_eff[b] = sum_k attn[b,k] * kernels[k]   (conv is linear in weights -> 4x fewer FLOPs)
__global__ void weff_kernel(const float* __restrict__ kern) {
    int b   = blockIdx.x / 576;           // 576 blocks per sample (589824/4/256)
    int blk = blockIdx.x % 576;
    size_t off = ((size_t)blk * 256 + threadIdx.x) * 4;
    float a0 = g_attn[b * 4 + 0], a1 = g_attn[b * 4 + 1];
    float a2 = g_attn[b * 4 + 2], a3 = g_attn[b * 4 + 3];
    float4 k0 = *(const float4*)(kern + off);
    float4 k1 = *(const float4*)(kern + (size_t)PER_B + off);
    float4 k2 = *(const float4*)(kern + (size_t)2 * PER_B + off);
    float4 k3 = *(const float4*)(kern + (size_t)3 * PER_B + off);
    float4 o;
    o.x = a0 * k0.x + a1 * k1.x + a2 * k2.x + a3 * k3.x;
    o.y = a0 * k0.y + a1 * k1.y + a2 * k2.y + a3 * k3.y;
    o.z = a0 * k0.z + a1 * k1.z + a2 * k2.z + a3 * k3.z;
    o.w = a0 * k0.w + a1 * k1.w + a2 * k2.w + a3 * k3.w;
    *(float4*)(g_weff + (size_t)b * PER_B + off) = o;
}

__global__ void beff_kernel(const float* __restrict__ biases) {
    int b = blockIdx.x, f = threadIdx.x;
    float s = 0.f;
    #pragma unroll
    for (int k = 0; k < NK; ++k) s += g_attn[b * 4 + k] * biases[k * F_ + f];
    g_beff[b * F_ + f] = s;
}

// ============ 4) Implicit-GEMM conv, per-sample weights ============
// GEMM per sample: M=3136 (hw), N=256 (f), K=2304 (r,s,c). BM=BN=128, BK=8.
// 256 threads, each computes 2x2 tiles of 4x4 (rows {ty*4, 64+ty*4}, cols {tx*4, 64+tx*4}).
__global__ __launch_bounds__(256, 2)
void conv_kernel(const float* __restrict__ x, float* __restrict__ out) {
    const int b   = blockIdx.z;
    const int bn0 = blockIdx.y * 128;
    const int bm0 = blockIdx.x * 128;
    const int t   = threadIdx.x;

    __shared__ float As[8][128];
    __shared__ float Bs[8][128];

    const float* xb = x + (size_t)b * HW * C_;
    const float* wb = g_weff + (size_t)b * PER_B;

    const int tx = t & 15;
    const int ty = t >> 4;

    // A-tile loader: 128 rows x 8 k -> thread loads one float4
    const int row_a = t >> 1;
    const int ka    = (t & 1) * 4;
    const int m  = bm0 + row_a;
    const int h  = m / 56;
    const int w  = m - h * 56;

    // B-tile loader: 8 k x 128 f -> thread loads one float4
    const int kb = t >> 5;
    const int fb = (t & 31) * 4;

    float acc[2][2][4][4];
    #pragma unroll
    for (int ri = 0; ri < 2; ++ri)
        #pragma unroll
        for (int ci = 0; ci < 2; ++ci)
            #pragma unroll
            for (int i = 0; i < 4; ++i)
                #pragma unroll
                for (int j = 0; j < 4; ++j) acc[ri][ci][i][j] = 0.f;

    // prefetch k-tile 0
    float4 av, bv;
    {
        const int rs = 0, cb = 0;
        const int r = rs / 3, s = rs % 3;
        int ih = h + r - 1, iw = w + s - 1;
        av = make_float4(0.f, 0.f, 0.f, 0.f);
        if (m < HW && (unsigned)ih < 56u && (unsigned)iw < 56u)
            av = *(const float4*)(xb + (size_t)(ih * 56 + iw) * C_ + cb + ka);
        bv = *(const float4*)(wb + (size_t)(0 + kb) * F_ + bn0 + fb);
    }

    for (int kt = 0; kt < KK / 8; ++kt) {
        // store current tile
        As[ka + 0][row_a] = av.x;
        As[ka + 1][row_a] = av.y;
        As[ka + 2][row_a] = av.z;
        As[ka + 3][row_a] = av.w;
        *(float4*)&Bs[kb][fb] = bv;
        __syncthreads();

        // prefetch next tile (overlap LDG with compute)
        if (kt + 1 < KK / 8) {
            const int kk0 = (kt + 1) * 8;
            const int rs  = kk0 >> 8;       // BK=8 divides 256 -> fixed (r,s) per tile
            const int cb  = kk0 & 255;
            const int r = rs / 3, s = rs - r * 3;
            int ih = h + r - 1, iw = w + s - 1;
            av = make_float4(0.f, 0.f, 0.f, 0.f);
            if (m < HW && (unsigned)ih < 56u && (unsigned)iw < 56u)
                av = *(const float4*)(xb + (size_t)(ih * 56 + iw) * C_ + cb + ka);
            bv = *(const float4*)(wb + (size_t)(kk0 + kb) * F_ + bn0 + fb);
        }

        // compute
        #pragma unroll
        for (int kk = 0; kk < 8; ++kk) {
            float4 a0 = *(const float4*)&As[kk][ty * 4];
            float4 a1 = *(const float4*)&As[kk][64 + ty * 4];
            float4 b0 = *(const float4*)&Bs[kk][tx * 4];
            float4 b1 = *(const float4*)&Bs[kk][64 + tx * 4];
            float ar[2][4] = {{a0.x, a0.y, a0.z, a0.w}, {a1.x, a1.y, a1.z, a1.w}};
            float br[2][4] = {{b0.x, b0.y, b0.z, b0.w}, {b1.x, b1.y, b1.z, b1.w}};
            #pragma unroll
            for (int ri = 0; ri < 2; ++ri)
                #pragma unroll
                for (int i = 0; i < 4; ++i)
                    #pragma unroll
                    for (int ci = 0; ci < 2; ++ci)
                        #pragma unroll
                        for (int j = 0; j < 4; ++j)
                            acc[ri][ci][i][j] += ar[ri][i] * br[ci][j];
        }
        __syncthreads();
    }

    // epilogue: + effective bias, write f32 NHWC
    float bias[2][4];
    #pragma unroll
    for (int ci = 0; ci < 2; ++ci)
        #pragma unroll
        for (int j = 0; j < 4; ++j)
            bias[ci][j] = g_beff[b * F_ + bn0 + ci * 64 + tx * 4 + j];

    float* ob = out + (size_t)b * HW * F_;
    #pragma unroll
    for (int ri = 0; ri < 2; ++ri) {
        #pragma unroll
        for (int i = 0; i < 4; ++i) {
            int mm = bm0 + ri * 64 + ty * 4 + i;
            if (mm < HW) {
                #pragma unroll
                for (int ci = 0; ci < 2; ++ci) {
                    float4 v;
                    v.x = acc[ri][ci][i][0] + bias[ci][0];
                    v.y = acc[ri][ci][i][1] + bias[ci][1];
                    v.z = acc[ri][ci][i][2] + bias[ci][2];
                    v.w = acc[ri][ci][i][3] + bias[ci][3];
                    *(float4*)(ob + (size_t)mm * F_ + bn0 + ci * 64 + tx * 4) = v;
                }
            }
        }
    }
}

// ============ launch ============
extern "C" void kernel_launch(void* const* d_in, const int* in_sizes, int n_in,
                              void* d_out, int out_size) {
    const float* x       = (const float*)d_in[0];   // [32,56,56,256]
    const float* kernels = (const float*)d_in[1];   // [4,3,3,256,256]
    const float* biases  = (const float*)d_in[2];   // [4,256]
    const float* w1      = (const float*)d_in[3];   // [256,64]
    const float* b1      = (const float*)d_in[4];   // [64]
    const float* w2      = (const float*)d_in[5];   // [64,4]
    const float* b2      = (const float*)d_in[6];   // [4]
    float* out = (float*)d_out;

    gap_partial_kernel<<<dim3(B_, 16), 256>>>(x);
    gap_final_kernel<<<B_, 256>>>();
    attn_kernel<<<B_, 64>>>(w1, b1, w2, b2);
    weff_kernel<<<B_ * 576, 256>>>(kernels);
    beff_kernel<<<B_, 256>>>(biases);
    conv_kernel<<<dim3(25, 2, B_), 256>>>(x, out);
}

// round 3
// speedup vs baseline: 2.7348x; 2.7348x over previous
#include <cuda_runtime.h>
#include <cstdint>

#define B_  32
#define HW  3136
#define C_  256
#define F_  256
#define KK  2304
#define NK  4
#define PER_B (KK*F_)

// ---------------- scratch (device globals) ----------------
__device__ float g_part[B_ * 16 * C_];
__device__ float g_pooled[B_ * C_];
__device__ float g_attn[B_ * NK];
__device__ float g_weff[(size_t)B_ * PER_B];   // [b][k][f], tf32-rounded
__device__ float g_beff[B_ * F_];

__device__ __forceinline__ float tf32r(float f) {
    float r; asm("cvt.rna.tf32.f32 %0, %1;" : "=f"(r) : "f"(f)); return r;
}

// ============ 1) GAP ============
__global__ void gap_partial_kernel(const float* __restrict__ x) {
    int b = blockIdx.x, chunk = blockIdx.y, c = threadIdx.x;
    const float* xb = x + (size_t)b * HW * C_;
    float s = 0.f;
    int p0 = chunk * 196;
    #pragma unroll 4
    for (int p = p0; p < p0 + 196; ++p) s += xb[(size_t)p * C_ + c];
    g_part[(b * 16 + chunk) * C_ + c] = s;
}
__global__ void gap_final_kernel() {
    int b = blockIdx.x, c = threadIdx.x;
    float s = 0.f;
    #pragma unroll
    for (int ch = 0; ch < 16; ++ch) s += g_part[(b * 16 + ch) * C_ + c];
    g_pooled[b * C_ + c] = s * (1.0f / 3136.0f);
}

// ============ 2) Router MLP + softmax ============
__global__ void attn_kernel(const float* __restrict__ w1, const float* __restrict__ b1,
                            const float* __restrict__ w2, const float* __restrict__ b2) {
    int b = blockIdx.x, j = threadIdx.x;
    __shared__ float sp[C_];
    __shared__ float sh[64];
    __shared__ float sl[NK];
    for (int c = j; c < C_; c += 64) sp[c] = g_pooled[b * C_ + c];
    __syncthreads();
    float acc = b1[j];
    #pragma unroll 4
    for (int c = 0; c < C_; ++c) acc += sp[c] * w1[c * 64 + j];
    sh[j] = fmaxf(acc, 0.f);
    __syncthreads();
    if (j < NK) {
        float lg = b2[j];
        #pragma unroll
        for (int i = 0; i < 64; ++i) lg += sh[i] * w2[i * NK + j];
        sl[j] = lg * (1.0f / 30.0f);
    }
    __syncthreads();
    if (j == 0) {
        float mx = fmaxf(fmaxf(sl[0], sl[1]), fmaxf(sl[2], sl[3]));
        float e0 = expf(sl[0] - mx), e1 = expf(sl[1] - mx);
        float e2 = expf(sl[2] - mx), e3 = expf(sl[3] - mx);
        float inv = 1.0f / (e0 + e1 + e2 + e3);
        g_attn[b * NK + 0] = e0 * inv; g_attn[b * NK + 1] = e1 * inv;
        g_attn[b * NK + 2] = e2 * inv; g_attn[b * NK + 3] = e3 * inv;
    }
}

// ============ 3) Effective weights [k][f] (tf32-rounded) + bias ============
__global__ void weff_kernel(const float* __restrict__ kern) {
    int b   = blockIdx.x / 576;
    int blk = blockIdx.x % 576;
    size_t off = ((size_t)blk * 256 + threadIdx.x) * 4;
    float a0 = g_attn[b * 4 + 0], a1 = g_attn[b * 4 + 1];
    float a2 = g_attn[b * 4 + 2], a3 = g_attn[b * 4 + 3];
    float4 k0 = *(const float4*)(kern + off);
    float4 k1 = *(const float4*)(kern + (size_t)PER_B + off);
    float4 k2 = *(const float4*)(kern + (size_t)2 * PER_B + off);
    float4 k3 = *(const float4*)(kern + (size_t)3 * PER_B + off);
    float4 o;
    o.x = tf32r(a0 * k0.x + a1 * k1.x + a2 * k2.x + a3 * k3.x);
    o.y = tf32r(a0 * k0.y + a1 * k1.y + a2 * k2.y + a3 * k3.y);
    o.z = tf32r(a0 * k0.z + a1 * k1.z + a2 * k2.z + a3 * k3.z);
    o.w = tf32r(a0 * k0.w + a1 * k1.w + a2 * k2.w + a3 * k3.w);
    *(float4*)(g_weff + (size_t)b * PER_B + off) = o;
}

__global__ void beff_kernel(const float* __restrict__ biases) {
    int b = blockIdx.x, f = threadIdx.x;
    float s = 0.f;
    #pragma unroll
    for (int k = 0; k < NK; ++k) s += g_attn[b * 4 + k] * biases[k * F_ + f];
    g_beff[b * F_ + f] = s;
}

// ============ 4) mma.sync tf32 implicit-GEMM conv ============
// BM=128, BN=128, BK=16; 8 warps (2x4); warp = 4x4 tiles of m16n8k8; 144 k-iters.
__device__ __forceinline__ void mma_tf32(float* d, const uint32_t* a, const uint32_t* bb) {
    asm volatile(
        "mma.sync.aligned.m16n8k8.row.col.f32.tf32.tf32.f32 "
        "{%0,%1,%2,%3},{%4,%5,%6,%7},{%8,%9},{%0,%1,%2,%3};"
        : "+f"(d[0]), "+f"(d[1]), "+f"(d[2]), "+f"(d[3])
        : "r"(a[0]), "r"(a[1]), "r"(a[2]), "r"(a[3]), "r"(bb[0]), "r"(bb[1]));
}

__global__ void __launch_bounds__(256, 2)
conv_mma(const float* __restrict__ x, float* __restrict__ out) {
    __shared__ __align__(16) float As[2][128][20];   // [row][k], pad 4
    __shared__ __align__(16) float Bs[2][16][132];   // [k][f],  pad 4

    const int t    = threadIdx.x;
    const int b    = blockIdx.z;
    const int bn0  = blockIdx.y * 128;
    const int bm0  = blockIdx.x * 128;
    const int lane = t & 31;
    const int warp = t >> 5;
    const int wm   = warp >> 2;          // 0..1  (64 rows each)
    const int wn   = warp & 3;           // 0..3  (32 cols each)

    const float* xb = x + (size_t)b * HW * C_;
    const float* wt = g_weff + (size_t)b * PER_B;

    // ---- A loader mapping: rows ar, ar+64; k-offset ak (16 floats/row via 4 thr) ----
    const int ar = t >> 2;
    const int ak = (t & 3) * 4;
    int m0 = bm0 + ar,      h0 = m0 / 56, w0 = m0 - h0 * 56;
    int m1 = bm0 + ar + 64, h1 = m1 / 56, w1 = m1 - h1 * 56;

    // ---- B loader mapping: k-rows bk, bk+8; 4 consecutive f at bn ----
    const int bk = t >> 5;
    const int bn = (t & 31) * 4;

    float acc[4][4][4];
    #pragma unroll
    for (int i = 0; i < 4; ++i)
        #pragma unroll
        for (int j = 0; j < 4; ++j)
            #pragma unroll
            for (int r = 0; r < 4; ++r) acc[i][j][r] = 0.f;

    float4 aR[2], bR[2];

    // prefetch kt = 0  (rs=0 -> rr=0, sc=0, dlt=-57, c0=0)
    {
        const int dlt = -57;
        int ih0 = h0 - 1, iw0 = w0 - 1;
        int ih1 = h1 - 1, iw1 = w1 - 1;
        aR[0] = make_float4(0.f, 0.f, 0.f, 0.f);
        aR[1] = make_float4(0.f, 0.f, 0.f, 0.f);
        if (m0 < HW && (unsigned)ih0 < 56u && (unsigned)iw0 < 56u)
            aR[0] = *(const float4*)(xb + (size_t)(m0 + dlt) * C_ + ak);
        if (m1 < HW && (unsigned)ih1 < 56u && (unsigned)iw1 < 56u)
            aR[1] = *(const float4*)(xb + (size_t)(m1 + dlt) * C_ + ak);
        bR[0] = *(const float4*)(wt + (size_t)(bk) * F_ + bn0 + bn);
        bR[1] = *(const float4*)(wt + (size_t)(bk + 8) * F_ + bn0 + bn);
    }

    #pragma unroll 1
    for (int kt = 0; kt < 144; ++kt) {
        const int st = kt & 1;

        // ---- STS current stage (A converted to tf32) ----
        *(float4*)&As[st][ar][ak]      = make_float4(tf32r(aR[0].x), tf32r(aR[0].y),
                                                     tf32r(aR[0].z), tf32r(aR[0].w));
        *(float4*)&As[st][ar + 64][ak] = make_float4(tf32r(aR[1].x), tf32r(aR[1].y),
                                                     tf32r(aR[1].z), tf32r(aR[1].w));
        *(float4*)&Bs[st][bk][bn]      = bR[0];
        *(float4*)&Bs[st][bk + 8][bn]  = bR[1];
        __syncthreads();

        // ---- prefetch next stage ----
        if (kt + 1 < 144) {
            const int kn = kt + 1;
            const int rs = kn >> 4;
            const int rr = rs / 3, sc = rs - rr * 3;
            const int dlt = (rr - 1) * 56 + (sc - 1);
            const int c0  = (kn & 15) << 4;
            int ih0 = h0 + rr - 1, iw0 = w0 + sc - 1;
            int ih1 = h1 + rr - 1, iw1 = w1 + sc - 1;
            aR[0] = make_float4(0.f, 0.f, 0.f, 0.f);
            aR[1] = make_float4(0.f, 0.f, 0.f, 0.f);
            if (m0 < HW && (unsigned)ih0 < 56u && (unsigned)iw0 < 56u)
                aR[0] = *(const float4*)(xb + (size_t)(m0 + dlt) * C_ + c0 + ak);
            if (m1 < HW && (unsigned)ih1 < 56u && (unsigned)iw1 < 56u)
                aR[1] = *(const float4*)(xb + (size_t)(m1 + dlt) * C_ + c0 + ak);
            bR[0] = *(const float4*)(wt + (size_t)(kn * 16 + bk) * F_ + bn0 + bn);
            bR[1] = *(const float4*)(wt + (size_t)(kn * 16 + bk + 8) * F_ + bn0 + bn);
        }

        // ---- compute: 2 k-steps of 8 ----
        #pragma unroll
        for (int ks = 0; ks < 2; ++ks) {
            const int ka = ks * 8 + (lane & 3);
            const int rb = wm * 64 + (lane >> 2);
            uint32_t afr[4][4];
            #pragma unroll
            for (int mt = 0; mt < 4; ++mt) {
                const int r = rb + mt * 16;
                afr[mt][0] = __float_as_uint(As[st][r][ka]);
                afr[mt][1] = __float_as_uint(As[st][r + 8][ka]);
                afr[mt][2] = __float_as_uint(As[st][r][ka + 4]);
                afr[mt][3] = __float_as_uint(As[st][r + 8][ka + 4]);
            }
            uint32_t bfr[4][2];
            const int nb = wn * 32 + (lane >> 2);
            #pragma unroll
            for (int nt = 0; nt < 4; ++nt) {
                const int n = nb + nt * 8;
                bfr[nt][0] = __float_as_uint(Bs[st][ka][n]);          // ka = ks*8 + lane%4
                bfr[nt][1] = __float_as_uint(Bs[st][ka + 4][n]);
            }
            #pragma unroll
            for (int mt = 0; mt < 4; ++mt)
                #pragma unroll
                for (int nt = 0; nt < 4; ++nt)
                    mma_tf32(acc[mt][nt], afr[mt], bfr[nt]);
        }
        __syncthreads();
    }

    // ---- epilogue: + bias, write f32 NHWC ----
    const int rb = bm0 + wm * 64 + (lane >> 2);
    const int cb = bn0 + wn * 32 + (lane & 3) * 2;
    #pragma unroll
    for (int nt = 0; nt < 4; ++nt) {
        const int cc = cb + nt * 8;
        const float bx = g_beff[b * F_ + cc];
        const float by = g_beff[b * F_ + cc + 1];
        #pragma unroll
        for (int mt = 0; mt < 4; ++mt) {
            const int r0 = rb + mt * 16;
            if (r0 < HW) {
                float2 v = make_float2(acc[mt][nt][0] + bx, acc[mt][nt][1] + by);
                *(float2*)(out + ((size_t)b * HW + r0) * F_ + cc) = v;
            }
            if (r0 + 8 < HW) {
                float2 v = make_float2(acc[mt][nt][2] + bx, acc[mt][nt][3] + by);
                *(float2*)(out + ((size_t)b * HW + r0 + 8) * F_ + cc) = v;
            }
        }
    }
}

// ============ launch ============
extern "C" void kernel_launch(void* const* d_in, const int* in_sizes, int n_in,
                              void* d_out, int out_size) {
    const float* x       = (const float*)d_in[0];
    const float* kernels = (const float*)d_in[1];
    const float* biases  = (const float*)d_in[2];
    const float* w1      = (const float*)d_in[3];
    const float* b1      = (const float*)d_in[4];
    const float* w2      = (const float*)d_in[5];
    const float* b2      = (const float*)d_in[6];
    float* out = (float*)d_out;

    gap_partial_kernel<<<dim3(B_, 16), 256>>>(x);
    gap_final_kernel<<<B_, 256>>>();
    attn_kernel<<<B_, 64>>>(w1, b1, w2, b2);
    weff_kernel<<<B_ * 576, 256>>>(kernels);
    beff_kernel<<<B_, 256>>>(biases);
    conv_mma<<<dim3(25, 2, B_), 256>>>(x, out);
}

// round 4
// speedup vs baseline: 3.1067x; 1.1360x over previous
#include <cuda_runtime.h>
#include <cuda_fp16.h>
#include <cstdint>

#define B_  32
#define HW  3136
#define C_  256
#define F_  256
#define KK  2304
#define NK  4
#define PER_B (KK*F_)
#define NKT 72                 // K chunks of 32
#define PH  40                 // smem pitch in halves (conflict-free: r*80 mod 128 distinct)

// ---------------- scratch ----------------
__device__ float g_part[B_ * 16 * C_];
__device__ float g_pooled[B_ * C_];
__device__ float g_attn[B_ * NK];
__device__ __half g_wth[(size_t)B_ * NKT * F_ * 32];   // packed [b][kt][f][k32], fp16
__device__ float g_beff[B_ * F_];

// ============ 1) GAP ============
__global__ void gap_partial_kernel(const float* __restrict__ x) {
    int b = blockIdx.x, chunk = blockIdx.y, c = threadIdx.x;
    const float* xb = x + (size_t)b * HW * C_;
    float s = 0.f;
    int p0 = chunk * 196;
    #pragma unroll 4
    for (int p = p0; p < p0 + 196; ++p) s += xb[(size_t)p * C_ + c];
    g_part[(b * 16 + chunk) * C_ + c] = s;
}
__global__ void gap_final_kernel() {
    int b = blockIdx.x, c = threadIdx.x;
    float s = 0.f;
    #pragma unroll
    for (int ch = 0; ch < 16; ++ch) s += g_part[(b * 16 + ch) * C_ + c];
    g_pooled[b * C_ + c] = s * (1.0f / 3136.0f);
}

// ============ 2) Router MLP + softmax ============
__global__ void attn_kernel(const float* __restrict__ w1, const float* __restrict__ b1,
                            const float* __restrict__ w2, const float* __restrict__ b2) {
    int b = blockIdx.x, j = threadIdx.x;
    __shared__ float sp[C_];
    __shared__ float sh[64];
    __shared__ float sl[NK];
    for (int c = j; c < C_; c += 64) sp[c] = g_pooled[b * C_ + c];
    __syncthreads();
    float acc = b1[j];
    #pragma unroll 4
    for (int c = 0; c < C_; ++c) acc += sp[c] * w1[c * 64 + j];
    sh[j] = fmaxf(acc, 0.f);
    __syncthreads();
    if (j < NK) {
        float lg = b2[j];
        #pragma unroll
        for (int i = 0; i < 64; ++i) lg += sh[i] * w2[i * NK + j];
        sl[j] = lg * (1.0f / 30.0f);
    }
    __syncthreads();
    if (j == 0) {
        float mx = fmaxf(fmaxf(sl[0], sl[1]), fmaxf(sl[2], sl[3]));
        float e0 = expf(sl[0] - mx), e1 = expf(sl[1] - mx);
        float e2 = expf(sl[2] - mx), e3 = expf(sl[3] - mx);
        float inv = 1.0f / (e0 + e1 + e2 + e3);
        g_attn[b * NK + 0] = e0 * inv; g_attn[b * NK + 1] = e1 * inv;
        g_attn[b * NK + 2] = e2 * inv; g_attn[b * NK + 3] = e3 * inv;
    }
}

// ============ 3) Effective weights: fp16, transposed + tile-packed [b][kt][f][k32] ============
__global__ void weff_t_kernel(const float* __restrict__ kern) {
    __shared__ float s[32][33];
    const int f0 = blockIdx.x * 32;
    const int kc = blockIdx.y;          // k chunk 0..71
    const int b  = blockIdx.z;
    const int t  = threadIdx.x;
    const int ty = t >> 3, tx = t & 7;
    float a0 = g_attn[b*4+0], a1 = g_attn[b*4+1], a2 = g_attn[b*4+2], a3 = g_attn[b*4+3];
    size_t base = (size_t)(kc * 32 + ty) * F_ + f0 + tx * 4;
    float4 v0 = *(const float4*)(kern + base);
    float4 v1 = *(const float4*)(kern + (size_t)PER_B + base);
    float4 v2 = *(const float4*)(kern + (size_t)2 * PER_B + base);
    float4 v3 = *(const float4*)(kern + (size_t)3 * PER_B + base);
    s[ty][tx*4+0] = a0*v0.x + a1*v1.x + a2*v2.x + a3*v3.x;
    s[ty][tx*4+1] = a0*v0.y + a1*v1.y + a2*v2.y + a3*v3.y;
    s[ty][tx*4+2] = a0*v0.z + a1*v1.z + a2*v2.z + a3*v3.z;
    s[ty][tx*4+3] = a0*v0.w + a1*v1.w + a2*v2.w + a3*v3.w;
    __syncthreads();
    // transpose: thread writes 4 k-halves for f-row (ty)
    __half2 h0 = __floats2half2_rn(s[tx*4+0][ty], s[tx*4+1][ty]);
    __half2 h1 = __floats2half2_rn(s[tx*4+2][ty], s[tx*4+3][ty]);
    uint2 pk = make_uint2(*(uint32_t*)&h0, *(uint32_t*)&h1);
    size_t o = (((size_t)(b * NKT + kc) * F_) + f0 + ty) * 32 + tx * 4;
    *(uint2*)(g_wth + o) = pk;
}

__global__ void beff_kernel(const float* __restrict__ biases) {
    int b = blockIdx.x, f = threadIdx.x;
    float s = 0.f;
    #pragma unroll
    for (int k = 0; k < NK; ++k) s += g_attn[b * 4 + k] * biases[k * F_ + f];
    g_beff[b * F_ + f] = s;
}

// ============ 4) fp16 mma.sync implicit-GEMM conv ============
__device__ __forceinline__ void ldm_x4(uint32_t* r, uint32_t addr) {
    asm volatile("ldmatrix.sync.aligned.m8n8.x4.shared.b16 {%0,%1,%2,%3}, [%4];"
        : "=r"(r[0]), "=r"(r[1]), "=r"(r[2]), "=r"(r[3]) : "r"(addr));
}
__device__ __forceinline__ void mma_f16(float* d, const uint32_t* a, const uint32_t* bb) {
    asm volatile(
        "mma.sync.aligned.m16n8k16.row.col.f32.f16.f16.f32 "
        "{%0,%1,%2,%3},{%4,%5,%6,%7},{%8,%9},{%0,%1,%2,%3};"
        : "+f"(d[0]), "+f"(d[1]), "+f"(d[2]), "+f"(d[3])
        : "r"(a[0]), "r"(a[1]), "r"(a[2]), "r"(a[3]), "r"(bb[0]), "r"(bb[1]));
}

__global__ void __launch_bounds__(256, 2)
conv_mma(const float* __restrict__ x, float* __restrict__ out) {
    __shared__ __align__(16) __half As[2][128][PH];   // [m][k]
    __shared__ __align__(16) __half Bs[2][128][PH];   // [n][k]

    const int t    = threadIdx.x;
    const int b    = blockIdx.z;
    const int bn0  = blockIdx.y * 128;
    const int bm0  = blockIdx.x * 128;
    const int lane = t & 31;
    const int warp = t >> 5;
    const int wm   = warp >> 2;          // 0..1 (64 rows)
    const int wn   = warp & 3;           // 0..3 (32 cols)

    const float* xb = x + (size_t)b * HW * C_;
    const __half* wth = g_wth + (size_t)b * NKT * F_ * 32;

    // ---- loaders: row = t&127, seg = t>>7 (16 halves each) ----
    const int lrow = t & 127;
    const int seg  = t >> 7;
    const int m0 = bm0 + lrow;
    const int h0 = m0 / 56, w0 = m0 - h0 * 56;

    // ---- ldmatrix lane addresses (byte offsets into stage 0) ----
    const uint32_t aSm = (uint32_t)__cvta_generic_to_shared(&As[0][0][0]);
    const uint32_t bSm = (uint32_t)__cvta_generic_to_shared(&Bs[0][0][0]);
    const uint32_t aLm = aSm + (uint32_t)(((wm * 64 + (lane & 15)) * PH + (lane >> 4) * 8) * 2);
    const uint32_t bLm = bSm + (uint32_t)(((wn * 32 + (lane & 7) + ((lane >> 4) & 1) * 8) * PH
                                           + ((lane >> 3) & 1) * 8) * 2);
    const uint32_t stA = (uint32_t)(128 * PH * 2);   // stage stride bytes

    // STS addresses
    const uint32_t aSt = aSm + (uint32_t)((lrow * PH + seg * 16) * 2);
    const uint32_t bSt = bSm + (uint32_t)((lrow * PH + seg * 16) * 2);

    float acc[4][4][4];
    #pragma unroll
    for (int i = 0; i < 4; ++i)
        #pragma unroll
        for (int j = 0; j < 4; ++j)
            #pragma unroll
            for (int r = 0; r < 4; ++r) acc[i][j][r] = 0.f;

    float4 aR[4];
    uint4  bR[2];

    // prefetch kt = 0 (rs=0: rr=0, sc=0, dlt=-57, c0=0)
    {
        int ih = h0 - 1, iw = w0 - 1;
        bool v = (m0 < HW) && ((unsigned)ih < 56u) && ((unsigned)iw < 56u);
        const float* pa = xb + (size_t)(m0 - 57) * C_ + seg * 16;
        #pragma unroll
        for (int q = 0; q < 4; ++q)
            aR[q] = v ? *(const float4*)(pa + q * 4) : make_float4(0.f, 0.f, 0.f, 0.f);
        const __half* pb = wth + ((size_t)0 * F_ + bn0 + lrow) * 32 + seg * 16;
        bR[0] = *(const uint4*)(pb);
        bR[1] = *(const uint4*)(pb + 8);
    }

    #pragma unroll 1
    for (int kt = 0; kt < NKT; ++kt) {
        const int st = kt & 1;
        const uint32_t so = st ? stA : 0u;

        // ---- STS current stage ----
        {
            __half2 h[8];
            #pragma unroll
            for (int q = 0; q < 4; ++q) {
                h[q*2+0] = __floats2half2_rn(aR[q].x, aR[q].y);
                h[q*2+1] = __floats2half2_rn(aR[q].z, aR[q].w);
            }
            uint4 u0 = make_uint4(*(uint32_t*)&h[0], *(uint32_t*)&h[1],
                                  *(uint32_t*)&h[2], *(uint32_t*)&h[3]);
            uint4 u1 = make_uint4(*(uint32_t*)&h[4], *(uint32_t*)&h[5],
                                  *(uint32_t*)&h[6], *(uint32_t*)&h[7]);
            asm volatile("st.shared.v4.b32 [%0], {%1,%2,%3,%4};" ::
                "r"(aSt + so), "r"(u0.x), "r"(u0.y), "r"(u0.z), "r"(u0.w) : "memory");
            asm volatile("st.shared.v4.b32 [%0], {%1,%2,%3,%4};" ::
                "r"(aSt + so + 16), "r"(u1.x), "r"(u1.y), "r"(u1.z), "r"(u1.w) : "memory");
            asm volatile("st.shared.v4.b32 [%0], {%1,%2,%3,%4};" ::
                "r"(bSt + so), "r"(bR[0].x), "r"(bR[0].y), "r"(bR[0].z), "r"(bR[0].w) : "memory");
            asm volatile("st.shared.v4.b32 [%0], {%1,%2,%3,%4};" ::
                "r"(bSt + so + 16), "r"(bR[1].x), "r"(bR[1].y), "r"(bR[1].z), "r"(bR[1].w) : "memory");
        }
        __syncthreads();

        // ---- prefetch next stage ----
        if (kt + 1 < NKT) {
            const int kn = kt + 1;
            const int rs = kn >> 3;
            const int rr = rs / 3, sc = rs - rr * 3;
            const int dlt = (rr - 1) * 56 + (sc - 1);
            const int c0  = (kn & 7) << 5;
            int ih = h0 + rr - 1, iw = w0 + sc - 1;
            bool v = (m0 < HW) && ((unsigned)ih < 56u) && ((unsigned)iw < 56u);
            const float* pa = xb + (size_t)(m0 + dlt) * C_ + c0 + seg * 16;
            #pragma unroll
            for (int q = 0; q < 4; ++q)
                aR[q] = v ? *(const float4*)(pa + q * 4) : make_float4(0.f, 0.f, 0.f, 0.f);
            const __half* pb = wth + ((size_t)kn * F_ + bn0 + lrow) * 32 + seg * 16;
            bR[0] = *(const uint4*)(pb);
            bR[1] = *(const uint4*)(pb + 8);
        }

        // ---- compute: 2 k-steps of 16 ----
        #pragma unroll
        for (int ks = 0; ks < 2; ++ks) {
            const uint32_t ko = (uint32_t)(ks * 16 * 2);
            uint32_t afr[4][4];
            #pragma unroll
            for (int mt = 0; mt < 4; ++mt)
                ldm_x4(afr[mt], aLm + so + (uint32_t)(mt * 16 * PH * 2) + ko);
            uint32_t bfr[2][4];   // [np][{b0t0,b1t0,b0t1,b1t1}]
            #pragma unroll
            for (int np = 0; np < 2; ++np)
                ldm_x4(bfr[np], bLm + so + (uint32_t)(np * 16 * PH * 2) + ko);
            #pragma unroll
            for (int mt = 0; mt < 4; ++mt) {
                #pragma unroll
                for (int nt = 0; nt < 4; ++nt)
                    mma_f16(acc[mt][nt], afr[mt], &bfr[nt >> 1][(nt & 1) * 2]);
            }
        }
        __syncthreads();
    }

    // ---- epilogue ----
    const int rb = bm0 + wm * 64 + (lane >> 2);
    const int cb = bn0 + wn * 32 + (lane & 3) * 2;
    #pragma unroll
    for (int nt = 0; nt < 4; ++nt) {
        const int cc = cb + nt * 8;
        const float bx = g_beff[b * F_ + cc];
        const float by = g_beff[b * F_ + cc + 1];
        #pragma unroll
        for (int mt = 0; mt < 4; ++mt) {
            const int r0 = rb + mt * 16;
            if (r0 < HW) {
                float2 v = make_float2(acc[mt][nt][0] + bx, acc[mt][nt][1] + by);
                *(float2*)(out + ((size_t)b * HW + r0) * F_ + cc) = v;
            }
            if (r0 + 8 < HW) {
                float2 v = make_float2(acc[mt][nt][2] + bx, acc[mt][nt][3] + by);
                *(float2*)(out + ((size_t)b * HW + r0 + 8) * F_ + cc) = v;
            }
        }
    }
}

// ============ launch ============
extern "C" void kernel_launch(void* const* d_in, const int* in_sizes, int n_in,
                              void* d_out, int out_size) {
    const float* x       = (const float*)d_in[0];
    const float* kernels = (const float*)d_in[1];
    const float* biases  = (const float*)d_in[2];
    const float* w1      = (const float*)d_in[3];
    const float* b1      = (const float*)d_in[4];
    const float* w2      = (const float*)d_in[5];
    const float* b2      = (const float*)d_in[6];
    float* out = (float*)d_out;

    gap_partial_kernel<<<dim3(B_, 16), 256>>>(x);
    gap_final_kernel<<<B_, 256>>>();
    attn_kernel<<<B_, 64>>>(w1, b1, w2, b2);
    weff_t_kernel<<<dim3(8, NKT, B_), 256>>>(kernels);
    beff_kernel<<<B_, 256>>>(biases);
    conv_mma<<<dim3(25, 2, B_), 256>>>(x, out);
}

// round 5
// speedup vs baseline: 3.2657x; 1.0512x over previous
#include <cuda_runtime.h>
#include <cuda_fp16.h>
#include <cstdint>

#define B_  32
#define HW  3136
#define C_  256
#define F_  256
#define NK  4
#define PER_B (2304*256)
#define NT  784            // 28x28 winograd tiles per sample
#define NTP 800            // padded tiles
#define PHW 40             // smem pitch (halves)

// ---------------- scratch ----------------
__device__ float g_part[B_ * 16 * C_];
__device__ float g_pooled[B_ * C_];
__device__ float g_attn[B_ * NK];
__device__ float g_beff[B_ * F_];
__device__ __half g_U[(size_t)B_ * 16 * F_ * C_];        // 67 MB  [b][xi][f][c]
__device__ __half g_V[(size_t)B_ * 16 * NTP * C_];       // 210 MB [b][xi][tile][c]

// ============ 1) GAP ============
__global__ void gap_partial_kernel(const float* __restrict__ x) {
    int b = blockIdx.x, chunk = blockIdx.y, c = threadIdx.x;
    const float* xb = x + (size_t)b * HW * C_;
    float s = 0.f;
    int p0 = chunk * 196;
    #pragma unroll 4
    for (int p = p0; p < p0 + 196; ++p) s += xb[(size_t)p * C_ + c];
    g_part[(b * 16 + chunk) * C_ + c] = s;
}
__global__ void gap_final_kernel() {
    int b = blockIdx.x, c = threadIdx.x;
    float s = 0.f;
    #pragma unroll
    for (int ch = 0; ch < 16; ++ch) s += g_part[(b * 16 + ch) * C_ + c];
    g_pooled[b * C_ + c] = s * (1.0f / 3136.0f);
}

// ============ 2) Router MLP + softmax ============
__global__ void attn_kernel(const float* __restrict__ w1, const float* __restrict__ b1,
                            const float* __restrict__ w2, const float* __restrict__ b2) {
    int b = blockIdx.x, j = threadIdx.x;
    __shared__ float sp[C_];
    __shared__ float sh[64];
    __shared__ float sl[NK];
    for (int c = j; c < C_; c += 64) sp[c] = g_pooled[b * C_ + c];
    __syncthreads();
    float acc = b1[j];
    #pragma unroll 4
    for (int c = 0; c < C_; ++c) acc += sp[c] * w1[c * 64 + j];
    sh[j] = fmaxf(acc, 0.f);
    __syncthreads();
    if (j < NK) {
        float lg = b2[j];
        #pragma unroll
        for (int i = 0; i < 64; ++i) lg += sh[i] * w2[i * NK + j];
        sl[j] = lg * (1.0f / 30.0f);
    }
    __syncthreads();
    if (j == 0) {
        float mx = fmaxf(fmaxf(sl[0], sl[1]), fmaxf(sl[2], sl[3]));
        float e0 = expf(sl[0] - mx), e1 = expf(sl[1] - mx);
        float e2 = expf(sl[2] - mx), e3 = expf(sl[3] - mx);
        float inv = 1.0f / (e0 + e1 + e2 + e3);
        g_attn[b * NK + 0] = e0 * inv; g_attn[b * NK + 1] = e1 * inv;
        g_attn[b * NK + 2] = e2 * inv; g_attn[b * NK + 3] = e3 * inv;
    }
}

__global__ void beff_kernel(const float* __restrict__ biases) {
    int b = blockIdx.x, f = threadIdx.x;
    float s = 0.f;
    #pragma unroll
    for (int k = 0; k < NK; ++k) s += g_attn[b * 4 + k] * biases[k * F_ + f];
    g_beff[b * F_ + f] = s;
}

// ============ 3) Weight transform: U = G (Σ attn_k w_k) G^T  → fp16 [b][xi][f][c] ============
__global__ void wtrans_kernel(const float* __restrict__ kern) {
    __shared__ float s[32][33];
    const int b  = blockIdx.z;
    const int f0 = blockIdx.x * 32;
    const int c0 = blockIdx.y * 32;
    const int t  = threadIdx.x;          // 1024 threads
    const int fl = t & 31, cl = t >> 5;
    float a0 = g_attn[b*4+0], a1 = g_attn[b*4+1], a2 = g_attn[b*4+2], a3 = g_attn[b*4+3];

    float g[3][3];
    const size_t base = (size_t)(c0 + cl) * F_ + f0 + fl;
    #pragma unroll
    for (int r = 0; r < 3; ++r)
        #pragma unroll
        for (int ss = 0; ss < 3; ++ss) {
            size_t o = (size_t)(r * 3 + ss) * (C_ * F_) + base;
            g[r][ss] = a0 * kern[o] + a1 * kern[(size_t)PER_B + o]
                     + a2 * kern[(size_t)2 * PER_B + o] + a3 * kern[(size_t)3 * PER_B + o];
        }
    float q[4][3];
    #pragma unroll
    for (int j = 0; j < 3; ++j) {
        q[0][j] = g[0][j];
        q[1][j] = 0.5f * (g[0][j] + g[1][j] + g[2][j]);
        q[2][j] = 0.5f * (g[0][j] - g[1][j] + g[2][j]);
        q[3][j] = g[2][j];
    }
    float u[4][4];
    #pragma unroll
    for (int i = 0; i < 4; ++i) {
        u[i][0] = q[i][0];
        u[i][1] = 0.5f * (q[i][0] + q[i][1] + q[i][2]);
        u[i][2] = 0.5f * (q[i][0] - q[i][1] + q[i][2]);
        u[i][3] = q[i][2];
    }
    #pragma unroll
    for (int xi = 0; xi < 16; ++xi) {
        __syncthreads();
        s[cl][fl] = u[xi >> 2][xi & 3];
        __syncthreads();
        float v = s[t & 31][t >> 5];     // (c = c0 + t&31, f = f0 + t>>5)
        g_U[((size_t)(b * 16 + xi) * F_ + f0 + (t >> 5)) * C_ + c0 + (t & 31)] = __float2half(v);
    }
}

// ============ 4) Input transform: V = B^T d B → fp16 [b][xi][tile][c] ============
__device__ __forceinline__ float4 f4add(float4 a, float4 b) {
    return make_float4(a.x+b.x, a.y+b.y, a.z+b.z, a.w+b.w);
}
__device__ __forceinline__ float4 f4sub(float4 a, float4 b) {
    return make_float4(a.x-b.x, a.y-b.y, a.z-b.z, a.w-b.w);
}

__global__ void itrans_kernel(const float* __restrict__ x) {
    const int b   = blockIdx.y;
    const int tl  = threadIdx.x >> 6;     // 0..3
    const int cg  = threadIdx.x & 63;     // c0 = cg*4
    const int tile = blockIdx.x * 4 + tl; // 0..799
    const int ti = tile / 28, tj = tile % 28;
    const int h0 = 2 * ti - 1, w0 = 2 * tj - 1;
    const bool tv = tile < NT;

    const float* xb = x + (size_t)b * HW * C_ + cg * 4;
    float4 d[4][4];
    #pragma unroll
    for (int i = 0; i < 4; ++i)
        #pragma unroll
        for (int j = 0; j < 4; ++j) {
            int ih = h0 + i, iw = w0 + j;
            bool v = tv && ((unsigned)ih < 56u) && ((unsigned)iw < 56u);
            d[i][j] = v ? *(const float4*)(xb + (size_t)(ih * 56 + iw) * C_)
                        : make_float4(0.f, 0.f, 0.f, 0.f);
        }

    // rows: T_nu = B^T d
    __half* Vb = g_V + ((size_t)(b * 16) * NTP + tile) * C_ + cg * 4;
    #pragma unroll
    for (int nu = 0; nu < 4; ++nu) {
        float4 T[4];
        #pragma unroll
        for (int j = 0; j < 4; ++j) {
            T[j] = (nu == 0) ? f4sub(d[0][j], d[2][j]) :
                   (nu == 1) ? f4add(d[1][j], d[2][j]) :
                   (nu == 2) ? f4sub(d[2][j], d[1][j]) :
                               f4sub(d[1][j], d[3][j]);
        }
        float4 V[4];
        V[0] = f4sub(T[0], T[2]);
        V[1] = f4add(T[1], T[2]);
        V[2] = f4sub(T[2], T[1]);
        V[3] = f4sub(T[1], T[3]);
        #pragma unroll
        for (int mu = 0; mu < 4; ++mu) {
            __half2 hlo = __floats2half2_rn(V[mu].x, V[mu].y);
            __half2 hhi = __floats2half2_rn(V[mu].z, V[mu].w);
            uint2 pk = make_uint2(*(uint32_t*)&hlo, *(uint32_t*)&hhi);
            *(uint2*)(Vb + (size_t)(nu * 4 + mu) * NTP * C_) = pk;
        }
    }
}

// ============ 5) Fused Winograd GEMM + inverse transform ============
__device__ __forceinline__ void ldm_x4(uint32_t* r, uint32_t addr) {
    asm volatile("ldmatrix.sync.aligned.m8n8.x4.shared.b16 {%0,%1,%2,%3}, [%4];"
        : "=r"(r[0]), "=r"(r[1]), "=r"(r[2]), "=r"(r[3]) : "r"(addr));
}
__device__ __forceinline__ void mma_f16(float* d, const uint32_t* a, const uint32_t* bb) {
    asm volatile(
        "mma.sync.aligned.m16n8k16.row.col.f32.f16.f16.f32 "
        "{%0,%1,%2,%3},{%4,%5,%6,%7},{%8,%9},{%0,%1,%2,%3};"
        : "+f"(d[0]), "+f"(d[1]), "+f"(d[2]), "+f"(d[3])
        : "r"(a[0]), "r"(a[1]), "r"(a[2]), "r"(a[3]), "r"(bb[0]), "r"(bb[1]));
}

// grid (25, 4, 32): tblk(32 tiles), fblk(64 f), b. 256 threads, 8 warps (2x4).
__global__ void __launch_bounds__(256, 2)
wino_gemm(float* __restrict__ out) {
    __shared__ __align__(16) __half As[2][64][PHW];   // U: [f][c]
    __shared__ __align__(16) __half Bs[2][32][PHW];   // V: [tile][c]

    const int t    = threadIdx.x;
    const int lane = t & 31;
    const int warp = t >> 5;
    const int wm   = warp >> 2;          // 0..1 : 32 f
    const int wn   = warp & 3;           // 0..3 : 8 tiles
    const int b    = blockIdx.z;
    const int f0   = blockIdx.y * 64;
    const int t0   = blockIdx.x * 32;

    const __half* Ub = g_U + (size_t)b * 16 * F_ * C_;
    const __half* Vb = g_V + (size_t)b * 16 * NTP * C_;

    // loaders: A = 64 rows x 32 halves (256 uint4), B = 32 rows (128 uint4)
    const int arow = t >> 2, aseg = t & 3;
    const bool bld = t < 128;

    const uint32_t aSm = (uint32_t)__cvta_generic_to_shared(&As[0][0][0]);
    const uint32_t bSm = (uint32_t)__cvta_generic_to_shared(&Bs[0][0][0]);
    const uint32_t aLm = aSm + (uint32_t)(((wm * 32 + (lane & 15)) * PHW + (lane >> 4) * 8) * 2);
    const uint32_t bLm = bSm + (uint32_t)(((wn * 8 + (lane & 7)) * PHW + (lane >> 3) * 8) * 2);
    const uint32_t aStg = (uint32_t)(64 * PHW * 2);
    const uint32_t bStg = (uint32_t)(32 * PHW * 2);
    const uint32_t aSt = aSm + (uint32_t)((arow * PHW + aseg * 8) * 2);
    const uint32_t bSt = bSm + (uint32_t)((arow * PHW + aseg * 8) * 2);

    float P[2][4];     // per-xi partial product (mt x d-regs)
    float o[4][2][4];  // [ij][mt][reg] inverse-transformed accumulators
    #pragma unroll
    for (int mt = 0; mt < 2; ++mt)
        #pragma unroll
        for (int r = 0; r < 4; ++r) P[mt][r] = 0.f;
    #pragma unroll
    for (int ij = 0; ij < 4; ++ij)
        #pragma unroll
        for (int mt = 0; mt < 2; ++mt)
            #pragma unroll
            for (int r = 0; r < 4; ++r) o[ij][mt][r] = 0.f;

    uint4 aR, bR;
    // prefetch it=0 (xi=0, kt=0)
    aR = *(const uint4*)(Ub + (size_t)(f0 + arow) * C_ + aseg * 8);
    if (bld) bR = *(const uint4*)(Vb + (size_t)(t0 + arow) * C_ + aseg * 8);

    #pragma unroll 1
    for (int it = 0; it < 128; ++it) {
        const int st = it & 1;
        // STS
        asm volatile("st.shared.v4.b32 [%0], {%1,%2,%3,%4};" ::
            "r"(aSt + st * aStg), "r"(aR.x), "r"(aR.y), "r"(aR.z), "r"(aR.w) : "memory");
        if (bld)
            asm volatile("st.shared.v4.b32 [%0], {%1,%2,%3,%4};" ::
                "r"(bSt + st * bStg), "r"(bR.x), "r"(bR.y), "r"(bR.z), "r"(bR.w) : "memory");
        __syncthreads();

        // prefetch next
        if (it + 1 < 128) {
            const int xi2 = (it + 1) >> 3;
            const int kt2 = (it + 1) & 7;
            aR = *(const uint4*)(Ub + (size_t)xi2 * (F_ * C_)
                                 + (size_t)(f0 + arow) * C_ + kt2 * 32 + aseg * 8);
            if (bld)
                bR = *(const uint4*)(Vb + (size_t)xi2 * (NTP * C_)
                                     + (size_t)(t0 + arow) * C_ + kt2 * 32 + aseg * 8);
        }

        // compute: B frag (both k-steps) + per-mt A frags
        {
            const uint32_t soA = st * aStg, soB = st * bStg;
            uint32_t bfr[4];
            ldm_x4(bfr, bLm + soB);
            #pragma unroll
            for (int mt = 0; mt < 2; ++mt) {
                uint32_t af0[4], af1[4];
                ldm_x4(af0, aLm + soA + (uint32_t)(mt * 16 * PHW * 2));
                ldm_x4(af1, aLm + soA + (uint32_t)(mt * 16 * PHW * 2) + 32);
                mma_f16(P[mt], af0, &bfr[0]);
                mma_f16(P[mt], af1, &bfr[2]);
            }
        }
        __syncthreads();

        // fold xi into output accumulators
        if ((it & 7) == 7) {
            const int xi = it >> 3;
            const int nu = xi >> 2, mu = xi & 3;
            const float a0n = (nu < 3) ? 1.f : 0.f;
            const float a1n = (nu == 0) ? 0.f : ((nu == 1) ? 1.f : -1.f);
            const float a0m = (mu < 3) ? 1.f : 0.f;
            const float a1m = (mu == 0) ? 0.f : ((mu == 1) ? 1.f : -1.f);
            const float c00 = a0n * a0m, c01 = a0n * a1m;
            const float c10 = a1n * a0m, c11 = a1n * a1m;
            #pragma unroll
            for (int mt = 0; mt < 2; ++mt)
                #pragma unroll
                for (int r = 0; r < 4; ++r) {
                    const float p = P[mt][r];
                    o[0][mt][r] += c00 * p;
                    o[1][mt][r] += c01 * p;
                    o[2][mt][r] += c10 * p;
                    o[3][mt][r] += c11 * p;
                    P[mt][r] = 0.f;
                }
        }
    }

    // ---- epilogue: write y (2x2 spatial per tile) + bias ----
    const int fr = f0 + wm * 32 + (lane >> 2);
    const int ta = t0 + wn * 8 + (lane & 3) * 2;
    float* ob = out + (size_t)b * HW * F_;
    const float* brow = g_beff + b * F_;
    #pragma unroll
    for (int mt = 0; mt < 2; ++mt) {
        #pragma unroll
        for (int rh = 0; rh < 2; ++rh) {
            const int f = fr + mt * 16 + rh * 8;
            const float bias = brow[f];
            #pragma unroll
            for (int cx = 0; cx < 2; ++cx) {
                const int tv = ta + cx;
                if (tv < NT) {
                    const int ti = tv / 28, tj = tv % 28;
                    const int r = rh * 2 + cx;
                    #pragma unroll
                    for (int i = 0; i < 2; ++i)
                        #pragma unroll
                        for (int j = 0; j < 2; ++j) {
                            const int h = 2 * ti + i, w = 2 * tj + j;
                            ob[(size_t)(h * 56 + w) * F_ + f] = o[i * 2 + j][mt][r] + bias;
                        }
                }
            }
        }
    }
}

// ============ launch ============
extern "C" void kernel_launch(void* const* d_in, const int* in_sizes, int n_in,
                              void* d_out, int out_size) {
    const float* x       = (const float*)d_in[0];
    const float* kernels = (const float*)d_in[1];
    const float* biases  = (const float*)d_in[2];
    const float* w1      = (const float*)d_in[3];
    const float* b1      = (const float*)d_in[4];
    const float* w2      = (const float*)d_in[5];
    const float* b2      = (const float*)d_in[6];
    float* out = (float*)d_out;

    gap_partial_kernel<<<dim3(B_, 16), 256>>>(x);
    gap_final_kernel<<<B_, 256>>>();
    attn_kernel<<<B_, 64>>>(w1, b1, w2, b2);
    beff_kernel<<<B_, 256>>>(biases);
    wtrans_kernel<<<dim3(8, 8, B_), 1024>>>(kernels);
    itrans_kernel<<<dim3(200, B_), 256>>>(x);
    wino_gemm<<<dim3(25, 4, B_), 256>>>(out);
}

// round 6
// speedup vs baseline: 4.5783x; 1.4019x over previous
#include <cuda_runtime.h>
#include <cuda_fp16.h>
#include <cstdint>

#define B_  32
#define HW  3136
#define C_  256
#define F_  256
#define NK  4
#define PER_B (2304*256)
#define NT  784            // 28x28 winograd tiles per sample
#define NTP 832            // padded tiles (13 blocks of 64)
#define PHW 40             // smem pitch (halves)

// ---------------- scratch ----------------
__device__ float g_part[B_ * 16 * C_];
__device__ float g_pooled[B_ * C_];
__device__ float g_attn[B_ * NK];
__device__ float g_beff[B_ * F_];
__device__ __half g_U[(size_t)B_ * 16 * F_ * C_];        // [b][xi][f][c]
__device__ __half g_V[(size_t)B_ * 16 * NTP * C_];       // [b][xi][tile][c]

// ============ 1) GAP ============
__global__ void gap_partial_kernel(const float* __restrict__ x) {
    int b = blockIdx.x, chunk = blockIdx.y, c = threadIdx.x;
    const float* xb = x + (size_t)b * HW * C_;
    float s = 0.f;
    int p0 = chunk * 196;
    #pragma unroll 4
    for (int p = p0; p < p0 + 196; ++p) s += xb[(size_t)p * C_ + c];
    g_part[(b * 16 + chunk) * C_ + c] = s;
}
__global__ void gap_final_kernel() {
    int b = blockIdx.x, c = threadIdx.x;
    float s = 0.f;
    #pragma unroll
    for (int ch = 0; ch < 16; ++ch) s += g_part[(b * 16 + ch) * C_ + c];
    g_pooled[b * C_ + c] = s * (1.0f / 3136.0f);
}

// ============ 2) Router MLP + softmax ============
__global__ void attn_kernel(const float* __restrict__ w1, const float* __restrict__ b1,
                            const float* __restrict__ w2, const float* __restrict__ b2) {
    int b = blockIdx.x, j = threadIdx.x;
    __shared__ float sp[C_];
    __shared__ float sh[64];
    __shared__ float sl[NK];
    for (int c = j; c < C_; c += 64) sp[c] = g_pooled[b * C_ + c];
    __syncthreads();
    float acc = b1[j];
    #pragma unroll 4
    for (int c = 0; c < C_; ++c) acc += sp[c] * w1[c * 64 + j];
    sh[j] = fmaxf(acc, 0.f);
    __syncthreads();
    if (j < NK) {
        float lg = b2[j];
        #pragma unroll
        for (int i = 0; i < 64; ++i) lg += sh[i] * w2[i * NK + j];
        sl[j] = lg * (1.0f / 30.0f);
    }
    __syncthreads();
    if (j == 0) {
        float mx = fmaxf(fmaxf(sl[0], sl[1]), fmaxf(sl[2], sl[3]));
        float e0 = expf(sl[0] - mx), e1 = expf(sl[1] - mx);
        float e2 = expf(sl[2] - mx), e3 = expf(sl[3] - mx);
        float inv = 1.0f / (e0 + e1 + e2 + e3);
        g_attn[b * NK + 0] = e0 * inv; g_attn[b * NK + 1] = e1 * inv;
        g_attn[b * NK + 2] = e2 * inv; g_attn[b * NK + 3] = e3 * inv;
    }
}

__global__ void beff_kernel(const float* __restrict__ biases) {
    int b = blockIdx.x, f = threadIdx.x;
    float s = 0.f;
    #pragma unroll
    for (int k = 0; k < NK; ++k) s += g_attn[b * 4 + k] * biases[k * F_ + f];
    g_beff[b * F_ + f] = s;
}

// ============ 3) Weight transform: U = G W G^T → fp16 [b][xi][f][c] ============
__global__ void wtrans_kernel(const float* __restrict__ kern) {
    __shared__ float s[32][33];
    const int b  = blockIdx.z;
    const int f0 = blockIdx.x * 32;
    const int c0 = blockIdx.y * 32;
    const int t  = threadIdx.x;          // 1024 threads
    const int fl = t & 31, cl = t >> 5;
    float a0 = g_attn[b*4+0], a1 = g_attn[b*4+1], a2 = g_attn[b*4+2], a3 = g_attn[b*4+3];

    float g[3][3];
    const size_t base = (size_t)(c0 + cl) * F_ + f0 + fl;
    #pragma unroll
    for (int r = 0; r < 3; ++r)
        #pragma unroll
        for (int ss = 0; ss < 3; ++ss) {
            size_t o = (size_t)(r * 3 + ss) * (C_ * F_) + base;
            g[r][ss] = a0 * kern[o] + a1 * kern[(size_t)PER_B + o]
                     + a2 * kern[(size_t)2 * PER_B + o] + a3 * kern[(size_t)3 * PER_B + o];
        }
    float q[4][3];
    #pragma unroll
    for (int j = 0; j < 3; ++j) {
        q[0][j] = g[0][j];
        q[1][j] = 0.5f * (g[0][j] + g[1][j] + g[2][j]);
        q[2][j] = 0.5f * (g[0][j] - g[1][j] + g[2][j]);
        q[3][j] = g[2][j];
    }
    float u[4][4];
    #pragma unroll
    for (int i = 0; i < 4; ++i) {
        u[i][0] = q[i][0];
        u[i][1] = 0.5f * (q[i][0] + q[i][1] + q[i][2]);
        u[i][2] = 0.5f * (q[i][0] - q[i][1] + q[i][2]);
        u[i][3] = q[i][2];
    }
    #pragma unroll
    for (int xi = 0; xi < 16; ++xi) {
        __syncthreads();
        s[cl][fl] = u[xi >> 2][xi & 3];
        __syncthreads();
        float v = s[t & 31][t >> 5];
        g_U[((size_t)(b * 16 + xi) * F_ + f0 + (t >> 5)) * C_ + c0 + (t & 31)] = __float2half(v);
    }
}

// ============ 4) Input transform: V = B^T d B → fp16 [b][xi][tile][c] ============
__device__ __forceinline__ float4 f4add(float4 a, float4 b) {
    return make_float4(a.x+b.x, a.y+b.y, a.z+b.z, a.w+b.w);
}
__device__ __forceinline__ float4 f4sub(float4 a, float4 b) {
    return make_float4(a.x-b.x, a.y-b.y, a.z-b.z, a.w-b.w);
}

__global__ void itrans_kernel(const float* __restrict__ x) {
    const int b   = blockIdx.y;
    const int tl  = threadIdx.x >> 6;
    const int cg  = threadIdx.x & 63;
    const int tile = blockIdx.x * 4 + tl;  // 0..831
    const int ti = tile / 28, tj = tile % 28;
    const int h0 = 2 * ti - 1, w0 = 2 * tj - 1;
    const bool tv = tile < NT;

    const float* xb = x + (size_t)b * HW * C_ + cg * 4;
    float4 d[4][4];
    #pragma unroll
    for (int i = 0; i < 4; ++i)
        #pragma unroll
        for (int j = 0; j < 4; ++j) {
            int ih = h0 + i, iw = w0 + j;
            bool v = tv && ((unsigned)ih < 56u) && ((unsigned)iw < 56u);
            d[i][j] = v ? *(const float4*)(xb + (size_t)(ih * 56 + iw) * C_)
                        : make_float4(0.f, 0.f, 0.f, 0.f);
        }

    __half* Vb = g_V + ((size_t)(b * 16) * NTP + tile) * C_ + cg * 4;
    #pragma unroll
    for (int nu = 0; nu < 4; ++nu) {
        float4 T[4];
        #pragma unroll
        for (int j = 0; j < 4; ++j) {
            T[j] = (nu == 0) ? f4sub(d[0][j], d[2][j]) :
                   (nu == 1) ? f4add(d[1][j], d[2][j]) :
                   (nu == 2) ? f4sub(d[2][j], d[1][j]) :
                               f4sub(d[1][j], d[3][j]);
        }
        float4 V[4];
        V[0] = f4sub(T[0], T[2]);
        V[1] = f4add(T[1], T[2]);
        V[2] = f4sub(T[2], T[1]);
        V[3] = f4sub(T[1], T[3]);
        #pragma unroll
        for (int mu = 0; mu < 4; ++mu) {
            __half2 hlo = __floats2half2_rn(V[mu].x, V[mu].y);
            __half2 hhi = __floats2half2_rn(V[mu].z, V[mu].w);
            uint2 pk = make_uint2(*(uint32_t*)&hlo, *(uint32_t*)&hhi);
            *(uint2*)(Vb + (size_t)(nu * 4 + mu) * NTP * C_) = pk;
        }
    }
}

// ============ 5) Fused Winograd GEMM + inverse transform ============
// CTA tile: 64 f x 64 tiles x BK=32. 8 warps (2x4): warp = 32 f x 16 tiles.
__device__ __forceinline__ void ldm_x4(uint32_t* r, uint32_t addr) {
    asm volatile("ldmatrix.sync.aligned.m8n8.x4.shared.b16 {%0,%1,%2,%3}, [%4];"
        : "=r"(r[0]), "=r"(r[1]), "=r"(r[2]), "=r"(r[3]) : "r"(addr));
}
__device__ __forceinline__ void mma_f16(float* d, const uint32_t* a, const uint32_t* bb) {
    asm volatile(
        "mma.sync.aligned.m16n8k16.row.col.f32.f16.f16.f32 "
        "{%0,%1,%2,%3},{%4,%5,%6,%7},{%8,%9},{%0,%1,%2,%3};"
        : "+f"(d[0]), "+f"(d[1]), "+f"(d[2]), "+f"(d[3])
        : "r"(a[0]), "r"(a[1]), "r"(a[2]), "r"(a[3]), "r"(bb[0]), "r"(bb[1]));
}

__global__ void __launch_bounds__(256, 2)
wino_gemm(float* __restrict__ out) {
    __shared__ __align__(16) __half As[2][64][PHW];   // U: [f][c]
    __shared__ __align__(16) __half Bs[2][64][PHW];   // V: [tile][c]

    const int t    = threadIdx.x;
    const int lane = t & 31;
    const int warp = t >> 5;
    const int wm   = warp >> 2;          // 0..1 : 32 f
    const int wn   = warp & 3;           // 0..3 : 16 tiles
    const int b    = blockIdx.z;
    const int f0   = blockIdx.y * 64;
    const int t0   = blockIdx.x * 64;

    const __half* Ub = g_U + (size_t)b * 16 * F_ * C_;
    const __half* Vb = g_V + (size_t)b * 16 * NTP * C_;

    // loaders: 64 rows x 32 halves each (256 x uint4); all threads load A and B
    const int arow = t >> 2, aseg = t & 3;

    const uint32_t aSm = (uint32_t)__cvta_generic_to_shared(&As[0][0][0]);
    const uint32_t bSm = (uint32_t)__cvta_generic_to_shared(&Bs[0][0][0]);
    const uint32_t aLm = aSm + (uint32_t)(((wm * 32 + (lane & 15)) * PHW + (lane >> 4) * 8) * 2);
    const uint32_t bLm = bSm + (uint32_t)(((wn * 16 + (lane & 7) + ((lane >> 4) & 1) * 8) * PHW
                                           + ((lane >> 3) & 1) * 8) * 2);
    const uint32_t aStg = (uint32_t)(64 * PHW * 2);
    const uint32_t aSt = aSm + (uint32_t)((arow * PHW + aseg * 8) * 2);
    const uint32_t bSt = bSm + (uint32_t)((arow * PHW + aseg * 8) * 2);

    float P[2][2][4];       // [mt][nt][reg]
    float o[4][2][2][4];    // [ij][mt][nt][reg]
    #pragma unroll
    for (int mt = 0; mt < 2; ++mt)
        #pragma unroll
        for (int nt = 0; nt < 2; ++nt)
            #pragma unroll
            for (int r = 0; r < 4; ++r) P[mt][nt][r] = 0.f;
    #pragma unroll
    for (int ij = 0; ij < 4; ++ij)
        #pragma unroll
        for (int mt = 0; mt < 2; ++mt)
            #pragma unroll
            for (int nt = 0; nt < 2; ++nt)
                #pragma unroll
                for (int r = 0; r < 4; ++r) o[ij][mt][nt][r] = 0.f;

    uint4 aR, bR;
    aR = *(const uint4*)(Ub + (size_t)(f0 + arow) * C_ + aseg * 8);
    bR = *(const uint4*)(Vb + (size_t)(t0 + arow) * C_ + aseg * 8);

    #pragma unroll 1
    for (int it = 0; it < 128; ++it) {
        const int st = it & 1;
        const uint32_t so = st * aStg;
        asm volatile("st.shared.v4.b32 [%0], {%1,%2,%3,%4};" ::
            "r"(aSt + so), "r"(aR.x), "r"(aR.y), "r"(aR.z), "r"(aR.w) : "memory");
        asm volatile("st.shared.v4.b32 [%0], {%1,%2,%3,%4};" ::
            "r"(bSt + so), "r"(bR.x), "r"(bR.y), "r"(bR.z), "r"(bR.w) : "memory");
        __syncthreads();

        // prefetch next stage
        if (it + 1 < 128) {
            const int xi2 = (it + 1) >> 3;
            const int kt2 = (it + 1) & 7;
            aR = *(const uint4*)(Ub + (size_t)xi2 * (F_ * C_)
                                 + (size_t)(f0 + arow) * C_ + kt2 * 32 + aseg * 8);
            bR = *(const uint4*)(Vb + (size_t)xi2 * (NTP * C_)
                                 + (size_t)(t0 + arow) * C_ + kt2 * 32 + aseg * 8);
        }

        // compute: 2 k-steps of 16; 8 MMAs per warp
        #pragma unroll
        for (int ks = 0; ks < 2; ++ks) {
            const uint32_t ko = (uint32_t)(ks * 32);   // 16 halves
            uint32_t bfr[4];
            ldm_x4(bfr, bLm + so + ko);
            #pragma unroll
            for (int mt = 0; mt < 2; ++mt) {
                uint32_t afr[4];
                ldm_x4(afr, aLm + so + (uint32_t)(mt * 16 * PHW * 2) + ko);
                mma_f16(P[mt][0], afr, &bfr[0]);
                mma_f16(P[mt][1], afr, &bfr[2]);
            }
        }
        __syncthreads();

        // fold xi into inverse-transform accumulators
        if ((it & 7) == 7) {
            const int xi = it >> 3;
            const int nu = xi >> 2, mu = xi & 3;
            const float a0n = (nu < 3) ? 1.f : 0.f;
            const float a1n = (nu == 0) ? 0.f : ((nu == 1) ? 1.f : -1.f);
            const float a0m = (mu < 3) ? 1.f : 0.f;
            const float a1m = (mu == 0) ? 0.f : ((mu == 1) ? 1.f : -1.f);
            const float c00 = a0n * a0m, c01 = a0n * a1m;
            const float c10 = a1n * a0m, c11 = a1n * a1m;
            #pragma unroll
            for (int mt = 0; mt < 2; ++mt)
                #pragma unroll
                for (int nt = 0; nt < 2; ++nt)
                    #pragma unroll
                    for (int r = 0; r < 4; ++r) {
                        const float p = P[mt][nt][r];
                        o[0][mt][nt][r] += c00 * p;
                        o[1][mt][nt][r] += c01 * p;
                        o[2][mt][nt][r] += c10 * p;
                        o[3][mt][nt][r] += c11 * p;
                        P[mt][nt][r] = 0.f;
                    }
        }
    }

    // ---- epilogue: 2x2 spatial per tile + bias ----
    float* ob = out + (size_t)b * HW * F_;
    const float* brow = g_beff + b * F_;
    #pragma unroll
    for (int mt = 0; mt < 2; ++mt) {
        #pragma unroll
        for (int rh = 0; rh < 2; ++rh) {
            const int f = f0 + wm * 32 + (lane >> 2) + mt * 16 + rh * 8;
            const float bias = brow[f];
            #pragma unroll
            for (int nt = 0; nt < 2; ++nt) {
                #pragma unroll
                for (int cx = 0; cx < 2; ++cx) {
                    const int tv = t0 + wn * 16 + nt * 8 + (lane & 3) * 2 + cx;
                    if (tv < NT) {
                        const int ti = tv / 28, tj = tv % 28;
                        const int r = rh * 2 + cx;
                        #pragma unroll
                        for (int i = 0; i < 2; ++i)
                            #pragma unroll
                            for (int j = 0; j < 2; ++j) {
                                const int h = 2 * ti + i, w = 2 * tj + j;
                                ob[(size_t)(h * 56 + w) * F_ + f] =
                                    o[i * 2 + j][mt][nt][r] + bias;
                            }
                    }
                }
            }
        }
    }
}

// ============ launch ============
extern "C" void kernel_launch(void* const* d_in, const int* in_sizes, int n_in,
                              void* d_out, int out_size) {
    const float* x       = (const float*)d_in[0];
    const float* kernels = (const float*)d_in[1];
    const float* biases  = (const float*)d_in[2];
    const float* w1      = (const float*)d_in[3];
    const float* b1      = (const float*)d_in[4];
    const float* w2      = (const float*)d_in[5];
    const float* b2      = (const float*)d_in[6];
    float* out = (float*)d_out;

    gap_partial_kernel<<<dim3(B_, 16), 256>>>(x);
    gap_final_kernel<<<B_, 256>>>();
    attn_kernel<<<B_, 64>>>(w1, b1, w2, b2);
    beff_kernel<<<B_, 256>>>(biases);
    wtrans_kernel<<<dim3(8, 8, B_), 1024>>>(kernels);
    itrans_kernel<<<dim3(208, B_), 256>>>(x);
    wino_gemm<<<dim3(13, 4, B_), 256>>>(out);
}

// round 7
// speedup vs baseline: 5.4293x; 1.1859x over previous
#include <cuda_runtime.h>
#include <cuda_fp16.h>
#include <cstdint>

#define B_  32
#define HW  3136
#define C_  256
#define F_  256
#define NK  4
#define PER_B (2304*256)
#define NT  784            // 28x28 winograd tiles per sample
#define NTP 832            // padded tiles (13 blocks of 64); pad region stays zero
#define PHW 40             // smem pitch (halves)
#define STGB (64*PHW*2)    // stage stride bytes (5120)

// ---------------- scratch ----------------
__device__ float g_part[B_ * 16 * C_];
__device__ float g_attn[B_ * NK];
__device__ float g_beff[B_ * F_];
__device__ __half g_U[(size_t)B_ * 16 * F_ * C_];        // [b][xi][f][c]
__device__ __half g_V[(size_t)B_ * 16 * NTP * C_];       // [b][xi][tile][c] (pad zero)

// ============ 1) GAP partial ============
__global__ void gap_partial_kernel(const float* __restrict__ x) {
    int b = blockIdx.x, chunk = blockIdx.y, c = threadIdx.x;
    const float* xb = x + (size_t)b * HW * C_;
    float s = 0.f;
    int p0 = chunk * 196;
    #pragma unroll 4
    for (int p = p0; p < p0 + 196; ++p) s += xb[(size_t)p * C_ + c];
    g_part[(b * 16 + chunk) * C_ + c] = s;
}

// ============ 2) Fused: GAP final + router MLP + softmax + beff ============
__global__ void router_kernel(const float* __restrict__ w1, const float* __restrict__ b1,
                              const float* __restrict__ w2, const float* __restrict__ b2,
                              const float* __restrict__ biases) {
    int b = blockIdx.x, t = threadIdx.x;   // 256 threads
    __shared__ float sp[C_];
    __shared__ float sh[64];
    __shared__ float sl[NK];
    __shared__ float sa[NK];
    float s = 0.f;
    #pragma unroll
    for (int ch = 0; ch < 16; ++ch) s += g_part[(b * 16 + ch) * C_ + t];
    sp[t] = s * (1.0f / 3136.0f);
    __syncthreads();
    if (t < 64) {
        float acc = b1[t];
        #pragma unroll 4
        for (int c = 0; c < C_; ++c) acc += sp[c] * w1[c * 64 + t];
        sh[t] = fmaxf(acc, 0.f);
    }
    __syncthreads();
    if (t < NK) {
        float lg = b2[t];
        #pragma unroll
        for (int i = 0; i < 64; ++i) lg += sh[i] * w2[i * NK + t];
        sl[t] = lg * (1.0f / 30.0f);
    }
    __syncthreads();
    if (t == 0) {
        float mx = fmaxf(fmaxf(sl[0], sl[1]), fmaxf(sl[2], sl[3]));
        float e0 = expf(sl[0] - mx), e1 = expf(sl[1] - mx);
        float e2 = expf(sl[2] - mx), e3 = expf(sl[3] - mx);
        float inv = 1.0f / (e0 + e1 + e2 + e3);
        sa[0] = e0 * inv; sa[1] = e1 * inv; sa[2] = e2 * inv; sa[3] = e3 * inv;
        g_attn[b * NK + 0] = sa[0]; g_attn[b * NK + 1] = sa[1];
        g_attn[b * NK + 2] = sa[2]; g_attn[b * NK + 3] = sa[3];
    }
    __syncthreads();
    float bs = 0.f;
    #pragma unroll
    for (int k = 0; k < NK; ++k) bs += sa[k] * biases[k * F_ + t];
    g_beff[b * F_ + t] = bs;
}

// ============ 3) Weight transform: U = G W G^T → fp16 [b][xi][f][c] ============
__global__ void wtrans_kernel(const float* __restrict__ kern) {
    __shared__ float s[32][33];
    const int b  = blockIdx.z;
    const int f0 = blockIdx.x * 32;
    const int c0 = blockIdx.y * 32;
    const int t  = threadIdx.x;          // 1024 threads
    const int fl = t & 31, cl = t >> 5;
    float a0 = g_attn[b*4+0], a1 = g_attn[b*4+1], a2 = g_attn[b*4+2], a3 = g_attn[b*4+3];

    float g[3][3];
    const size_t base = (size_t)(c0 + cl) * F_ + f0 + fl;
    #pragma unroll
    for (int r = 0; r < 3; ++r)
        #pragma unroll
        for (int ss = 0; ss < 3; ++ss) {
            size_t o = (size_t)(r * 3 + ss) * (C_ * F_) + base;
            g[r][ss] = a0 * kern[o] + a1 * kern[(size_t)PER_B + o]
                     + a2 * kern[(size_t)2 * PER_B + o] + a3 * kern[(size_t)3 * PER_B + o];
        }
    float q[4][3];
    #pragma unroll
    for (int j = 0; j < 3; ++j) {
        q[0][j] = g[0][j];
        q[1][j] = 0.5f * (g[0][j] + g[1][j] + g[2][j]);
        q[2][j] = 0.5f * (g[0][j] - g[1][j] + g[2][j]);
        q[3][j] = g[2][j];
    }
    float u[4][4];
    #pragma unroll
    for (int i = 0; i < 4; ++i) {
        u[i][0] = q[i][0];
        u[i][1] = 0.5f * (q[i][0] + q[i][1] + q[i][2]);
        u[i][2] = 0.5f * (q[i][0] - q[i][1] + q[i][2]);
        u[i][3] = q[i][2];
    }
    #pragma unroll
    for (int xi = 0; xi < 16; ++xi) {
        __syncthreads();
        s[cl][fl] = u[xi >> 2][xi & 3];
        __syncthreads();
        float v = s[t & 31][t >> 5];
        g_U[((size_t)(b * 16 + xi) * F_ + f0 + (t >> 5)) * C_ + c0 + (t & 31)] = __float2half(v);
    }
}

// ============ 4) Input transform (smem-tiled): V = B^T d B → fp16 ============
// Block: 7x7 tile patch (16x16 pixels) x 32 channels. Grid (16, 8, 32).
__global__ void __launch_bounds__(256)
itrans_kernel(const float* __restrict__ x) {
    __shared__ float sx[16 * 16 * 32];   // 32 KB
    const int b  = blockIdx.z;
    const int c0 = blockIdx.y * 32;
    const int pi = blockIdx.x >> 2, pj = blockIdx.x & 3;
    const int ti0 = pi * 7, tj0 = pj * 7;
    const int t = threadIdx.x;

    const float* xb = x + (size_t)b * HW * C_ + c0;
    // load 16x16 px x 32c: 2048 float4 units, 8 per thread
    #pragma unroll
    for (int p = 0; p < 8; ++p) {
        int u  = p * 256 + t;
        int px = u >> 3, cu = u & 7;
        int rp = px >> 4, cp = px & 15;
        int ih = 2 * ti0 - 1 + rp, iw = 2 * tj0 - 1 + cp;
        float4 v = make_float4(0.f, 0.f, 0.f, 0.f);
        if ((unsigned)ih < 56u && (unsigned)iw < 56u)
            v = *(const float4*)(xb + (size_t)(ih * 56 + iw) * C_ + cu * 4);
        *(float4*)(sx + px * 32 + cu * 4) = v;
    }
    __syncthreads();

    // 49 tiles x 8 c-groups = 392 items
    for (int item = t; item < 392; item += 256) {
        const int tile = item >> 3, cg = item & 7;
        const int lti = tile / 7, ltj = tile % 7;

        float4 d[4][4];
        #pragma unroll
        for (int i = 0; i < 4; ++i)
            #pragma unroll
            for (int j = 0; j < 4; ++j) {
                int px = (2 * lti + i) * 16 + (2 * ltj + j);
                d[i][j] = *(const float4*)(sx + px * 32 + cg * 4);
            }

        const int tg = (ti0 + lti) * 28 + (tj0 + ltj);
        __half* Vb = g_V + ((size_t)(b * 16) * NTP + tg) * C_ + c0 + cg * 4;
        #pragma unroll
        for (int nu = 0; nu < 4; ++nu) {
            float4 T[4];
            #pragma unroll
            for (int j = 0; j < 4; ++j) {
                T[j] = (nu == 0) ? make_float4(d[0][j].x-d[2][j].x, d[0][j].y-d[2][j].y,
                                               d[0][j].z-d[2][j].z, d[0][j].w-d[2][j].w) :
                       (nu == 1) ? make_float4(d[1][j].x+d[2][j].x, d[1][j].y+d[2][j].y,
                                               d[1][j].z+d[2][j].z, d[1][j].w+d[2][j].w) :
                       (nu == 2) ? make_float4(d[2][j].x-d[1][j].x, d[2][j].y-d[1][j].y,
                                               d[2][j].z-d[1][j].z, d[2][j].w-d[1][j].w) :
                                   make_float4(d[1][j].x-d[3][j].x, d[1][j].y-d[3][j].y,
                                               d[1][j].z-d[3][j].z, d[1][j].w-d[3][j].w);
            }
            float4 V[4];
            V[0] = make_float4(T[0].x-T[2].x, T[0].y-T[2].y, T[0].z-T[2].z, T[0].w-T[2].w);
            V[1] = make_float4(T[1].x+T[2].x, T[1].y+T[2].y, T[1].z+T[2].z, T[1].w+T[2].w);
            V[2] = make_float4(T[2].x-T[1].x, T[2].y-T[1].y, T[2].z-T[1].z, T[2].w-T[1].w);
            V[3] = make_float4(T[1].x-T[3].x, T[1].y-T[3].y, T[1].z-T[3].z, T[1].w-T[3].w);
            #pragma unroll
            for (int mu = 0; mu < 4; ++mu) {
                __half2 hlo = __floats2half2_rn(V[mu].x, V[mu].y);
                __half2 hhi = __floats2half2_rn(V[mu].z, V[mu].w);
                uint2 pk = make_uint2(*(uint32_t*)&hlo, *(uint32_t*)&hhi);
                *(uint2*)(Vb + (size_t)(nu * 4 + mu) * NTP * C_) = pk;
            }
        }
    }
}

// ============ 5) Fused Winograd GEMM + inverse transform (3-stage cp.async) ============
__device__ __forceinline__ void ldm_x4(uint32_t* r, uint32_t addr) {
    asm volatile("ldmatrix.sync.aligned.m8n8.x4.shared.b16 {%0,%1,%2,%3}, [%4];"
        : "=r"(r[0]), "=r"(r[1]), "=r"(r[2]), "=r"(r[3]) : "r"(addr));
}
__device__ __forceinline__ void mma_f16(float* d, const uint32_t* a, const uint32_t* bb) {
    asm volatile(
        "mma.sync.aligned.m16n8k16.row.col.f32.f16.f16.f32 "
        "{%0,%1,%2,%3},{%4,%5,%6,%7},{%8,%9},{%0,%1,%2,%3};"
        : "+f"(d[0]), "+f"(d[1]), "+f"(d[2]), "+f"(d[3])
        : "r"(a[0]), "r"(a[1]), "r"(a[2]), "r"(a[3]), "r"(bb[0]), "r"(bb[1]));
}
__device__ __forceinline__ void cpa16(uint32_t s, const void* g) {
    asm volatile("cp.async.ca.shared.global [%0], [%1], 16;" :: "r"(s), "l"(g) : "memory");
}

__global__ void __launch_bounds__(256, 2)
wino_gemm(float* __restrict__ out) {
    __shared__ __align__(16) __half As[3][64][PHW];   // U: [f][c]
    __shared__ __align__(16) __half Bs[3][64][PHW];   // V: [tile][c]

    const int t    = threadIdx.x;
    const int lane = t & 31;
    const int warp = t >> 5;
    const int wm   = warp >> 2;          // 0..1 : 32 f
    const int wn   = warp & 3;           // 0..3 : 16 tiles
    const int b    = blockIdx.z;
    const int f0   = blockIdx.y * 64;
    const int t0   = blockIdx.x * 64;

    const __half* Ub = g_U + (size_t)b * 16 * F_ * C_;
    const __half* Vb = g_V + (size_t)b * 16 * NTP * C_;

    const int arow = t >> 2, aseg = t & 3;

    const uint32_t aSm = (uint32_t)__cvta_generic_to_shared(&As[0][0][0]);
    const uint32_t bSm = (uint32_t)__cvta_generic_to_shared(&Bs[0][0][0]);
    const uint32_t aLm = aSm + (uint32_t)(((wm * 32 + (lane & 15)) * PHW + (lane >> 4) * 8) * 2);
    const uint32_t bLm = bSm + (uint32_t)(((wn * 16 + (lane & 7) + ((lane >> 4) & 1) * 8) * PHW
                                           + ((lane >> 3) & 1) * 8) * 2);
    const uint32_t aDst = aSm + (uint32_t)((arow * PHW + aseg * 8) * 2);
    const uint32_t bDst = bSm + (uint32_t)((arow * PHW + aseg * 8) * 2);
    const __half* gaB = Ub + (size_t)(f0 + arow) * C_ + aseg * 8;
    const __half* gbB = Vb + (size_t)(t0 + arow) * C_ + aseg * 8;

    float P[2][2][4];
    float o[4][2][2][4];
    #pragma unroll
    for (int mt = 0; mt < 2; ++mt)
        #pragma unroll
        for (int nt = 0; nt < 2; ++nt)
            #pragma unroll
            for (int r = 0; r < 4; ++r) P[mt][nt][r] = 0.f;
    #pragma unroll
    for (int ij = 0; ij < 4; ++ij)
        #pragma unroll
        for (int mt = 0; mt < 2; ++mt)
            #pragma unroll
            for (int nt = 0; nt < 2; ++nt)
                #pragma unroll
                for (int r = 0; r < 4; ++r) o[ij][mt][nt][r] = 0.f;

    // prologue: stages 0,1 <- indices 0,1
    #pragma unroll
    for (int j = 0; j < 2; ++j) {
        const int xi = j >> 3, kt = j & 7;
        cpa16(aDst + j * STGB, gaB + (size_t)xi * (F_ * C_) + kt * 32);
        cpa16(bDst + j * STGB, gbB + (size_t)xi * (NTP * C_) + kt * 32);
        asm volatile("cp.async.commit_group;" ::: "memory");
    }

    int cur = 0;
    #pragma unroll 1
    for (int it = 0; it < 128; ++it) {
        asm volatile("cp.async.wait_group 1;" ::: "memory");
        __syncthreads();

        const uint32_t so = (uint32_t)(cur * STGB);
        #pragma unroll
        for (int ks = 0; ks < 2; ++ks) {
            const uint32_t ko = (uint32_t)(ks * 32);
            uint32_t bfr[4];
            ldm_x4(bfr, bLm + so + ko);
            #pragma unroll
            for (int mt = 0; mt < 2; ++mt) {
                uint32_t afr[4];
                ldm_x4(afr, aLm + so + (uint32_t)(mt * 16 * PHW * 2) + ko);
                mma_f16(P[mt][0], afr, &bfr[0]);
                mma_f16(P[mt][1], afr, &bfr[2]);
            }
        }

        // fold xi into inverse-transform accumulators
        if ((it & 7) == 7) {
            const int xi = it >> 3;
            const int nu = xi >> 2, mu = xi & 3;
            const float a0n = (nu < 3) ? 1.f : 0.f;
            const float a1n = (nu == 0) ? 0.f : ((nu == 1) ? 1.f : -1.f);
            const float a0m = (mu < 3) ? 1.f : 0.f;
            const float a1m = (mu == 0) ? 0.f : ((mu == 1) ? 1.f : -1.f);
            const float c00 = a0n * a0m, c01 = a0n * a1m;
            const float c10 = a1n * a0m, c11 = a1n * a1m;
            #pragma unroll
            for (int mt = 0; mt < 2; ++mt)
                #pragma unroll
                for (int nt = 0; nt < 2; ++nt)
                    #pragma unroll
                    for (int r = 0; r < 4; ++r) {
                        const float p = P[mt][nt][r];
                        o[0][mt][nt][r] += c00 * p;
                        o[1][mt][nt][r] += c01 * p;
                        o[2][mt][nt][r] += c10 * p;
                        o[3][mt][nt][r] += c11 * p;
                        P[mt][nt][r] = 0.f;
                    }
        }

        // issue next stage (safe: barrier above ordered all compute(it-1))
        if (it + 2 < 128) {
            const int j  = it + 2;
            const int xi = j >> 3, kt = j & 7;
            int ns = cur + 2; if (ns >= 3) ns -= 3;
            cpa16(aDst + ns * STGB, gaB + (size_t)xi * (F_ * C_) + kt * 32);
            cpa16(bDst + ns * STGB, gbB + (size_t)xi * (NTP * C_) + kt * 32);
        }
        asm volatile("cp.async.commit_group;" ::: "memory");
        if (++cur == 3) cur = 0;
    }

    // ---- epilogue: 2x2 spatial per tile + bias ----
    float* ob = out + (size_t)b * HW * F_;
    const float* brow = g_beff + b * F_;
    #pragma unroll
    for (int mt = 0; mt < 2; ++mt) {
        #pragma unroll
        for (int rh = 0; rh < 2; ++rh) {
            const int f = f0 + wm * 32 + (lane >> 2) + mt * 16 + rh * 8;
            const float bias = brow[f];
            #pragma unroll
            for (int nt = 0; nt < 2; ++nt) {
                #pragma unroll
                for (int cx = 0; cx < 2; ++cx) {
                    const int tv = t0 + wn * 16 + nt * 8 + (lane & 3) * 2 + cx;
                    if (tv < NT) {
                        const int ti = tv / 28, tj = tv % 28;
                        const int r = rh * 2 + cx;
                        #pragma unroll
                        for (int i = 0; i < 2; ++i)
                            #pragma unroll
                            for (int j = 0; j < 2; ++j) {
                                const int h = 2 * ti + i, w = 2 * tj + j;
                                ob[(size_t)(h * 56 + w) * F_ + f] =
                                    o[i * 2 + j][mt][nt][r] + bias;
                            }
                    }
                }
            }
        }
    }
}

// ============ launch ============
extern "C" void kernel_launch(void* const* d_in, const int* in_sizes, int n_in,
                              void* d_out, int out_size) {
    const float* x       = (const float*)d_in[0];
    const float* kernels = (const float*)d_in[1];
    const float* biases  = (const float*)d_in[2];
    const float* w1      = (const float*)d_in[3];
    const float* b1      = (const float*)d_in[4];
    const float* w2      = (const float*)d_in[5];
    const float* b2      = (const float*)d_in[6];
    float* out = (float*)d_out;

    gap_partial_kernel<<<dim3(B_, 16), 256>>>(x);
    router_kernel<<<B_, 256>>>(w1, b1, w2, b2, biases);
    wtrans_kernel<<<dim3(8, 8, B_), 1024>>>(kernels);
    itrans_kernel<<<dim3(16, 8, B_), 256>>>(x);
    wino_gemm<<<dim3(13, 4, B_), 256>>>(out);
}

// round 8
// speedup vs baseline: 6.0110x; 1.1071x over previous
#include <cuda_runtime.h>
#include <cuda_fp16.h>
#include <cstdint>

#define B_  32
#define HW  3136
#define C_  256
#define F_  256
#define NK  4
#define PER_B (2304*256)
#define NT  784            // 28x28 winograd tiles per sample
#define NTP 832            // padded tiles (13 blocks of 64); pad region stays zero
#define PHW 40             // smem pitch (halves)
#define STGB (64*PHW*2)    // stage stride bytes (5120)

// ---------------- scratch ----------------
__device__ float g_part[B_ * 16 * C_];
__device__ float g_attn[B_ * NK];
__device__ float g_beff[B_ * F_];
__device__ __half g_U[(size_t)B_ * 16 * F_ * C_];        // [b][xi][f][c]
__device__ __half g_V[(size_t)B_ * 16 * NTP * C_];       // [b][xi][tile][c] (pad zero)

// ============ 1) Input transform (smem-tiled) + fused GAP partial ============
// Block: 7x7 tile patch (16x16 pixels) x 32 channels. Grid (16, 8, 32).
__global__ void __launch_bounds__(256)
itrans_kernel(const float* __restrict__ x) {
    __shared__ float sx[16 * 16 * 32];   // 32 KB
    __shared__ float red[8][32];
    const int b  = blockIdx.z;
    const int c0 = blockIdx.y * 32;
    const int pi = blockIdx.x >> 2, pj = blockIdx.x & 3;
    const int ti0 = pi * 7, tj0 = pj * 7;
    const int t = threadIdx.x;

    const float* xb = x + (size_t)b * HW * C_ + c0;
    // load 16x16 px x 32c: 2048 float4 units, 8 per thread
    #pragma unroll
    for (int p = 0; p < 8; ++p) {
        int u  = p * 256 + t;
        int px = u >> 3, cu = u & 7;
        int rp = px >> 4, cp = px & 15;
        int ih = 2 * ti0 - 1 + rp, iw = 2 * tj0 - 1 + cp;
        float4 v = make_float4(0.f, 0.f, 0.f, 0.f);
        if ((unsigned)ih < 56u && (unsigned)iw < 56u)
            v = *(const float4*)(xb + (size_t)(ih * 56 + iw) * C_ + cu * 4);
        *(float4*)(sx + px * 32 + cu * 4) = v;
    }
    __syncthreads();

    // ---- fused GAP partial over exclusive 14x14 interior ----
    {
        const int part = t >> 5, cl = t & 31;
        float ps = 0.f;
        for (int i = part; i < 196; i += 8) {
            int rp = 1 + i / 14, cp = 1 + i % 14;
            ps += sx[(rp * 16 + cp) * 32 + cl];
        }
        red[part][cl] = ps;
    }
    __syncthreads();
    if (t < 32) {
        float s = 0.f;
        #pragma unroll
        for (int r = 0; r < 8; ++r) s += red[r][t];
        g_part[(b * 16 + blockIdx.x) * C_ + c0 + t] = s;
    }

    // ---- 49 tiles x 8 c-groups = 392 transform items ----
    for (int item = t; item < 392; item += 256) {
        const int tile = item >> 3, cg = item & 7;
        const int lti = tile / 7, ltj = tile % 7;

        float4 d[4][4];
        #pragma unroll
        for (int i = 0; i < 4; ++i)
            #pragma unroll
            for (int j = 0; j < 4; ++j) {
                int px = (2 * lti + i) * 16 + (2 * ltj + j);
                d[i][j] = *(const float4*)(sx + px * 32 + cg * 4);
            }

        const int tg = (ti0 + lti) * 28 + (tj0 + ltj);
        __half* Vb = g_V + ((size_t)(b * 16) * NTP + tg) * C_ + c0 + cg * 4;
        #pragma unroll
        for (int nu = 0; nu < 4; ++nu) {
            float4 T[4];
            #pragma unroll
            for (int j = 0; j < 4; ++j) {
                T[j] = (nu == 0) ? make_float4(d[0][j].x-d[2][j].x, d[0][j].y-d[2][j].y,
                                               d[0][j].z-d[2][j].z, d[0][j].w-d[2][j].w) :
                       (nu == 1) ? make_float4(d[1][j].x+d[2][j].x, d[1][j].y+d[2][j].y,
                                               d[1][j].z+d[2][j].z, d[1][j].w+d[2][j].w) :
                       (nu == 2) ? make_float4(d[2][j].x-d[1][j].x, d[2][j].y-d[1][j].y,
                                               d[2][j].z-d[1][j].z, d[2][j].w-d[1][j].w) :
                                   make_float4(d[1][j].x-d[3][j].x, d[1][j].y-d[3][j].y,
                                               d[1][j].z-d[3][j].z, d[1][j].w-d[3][j].w);
            }
            float4 V[4];
            V[0] = make_float4(T[0].x-T[2].x, T[0].y-T[2].y, T[0].z-T[2].z, T[0].w-T[2].w);
            V[1] = make_float4(T[1].x+T[2].x, T[1].y+T[2].y, T[1].z+T[2].z, T[1].w+T[2].w);
            V[2] = make_float4(T[2].x-T[1].x, T[2].y-T[1].y, T[2].z-T[1].z, T[2].w-T[1].w);
            V[3] = make_float4(T[1].x-T[3].x, T[1].y-T[3].y, T[1].z-T[3].z, T[1].w-T[3].w);
            #pragma unroll
            for (int mu = 0; mu < 4; ++mu) {
                __half2 hlo = __floats2half2_rn(V[mu].x, V[mu].y);
                __half2 hhi = __floats2half2_rn(V[mu].z, V[mu].w);
                uint2 pk = make_uint2(*(uint32_t*)&hlo, *(uint32_t*)&hhi);
                *(uint2*)(Vb + (size_t)(nu * 4 + mu) * NTP * C_) = pk;
            }
        }
    }
}

// ============ 2) Fused: GAP final + router MLP + softmax + beff ============
__global__ void router_kernel(const float* __restrict__ w1, const float* __restrict__ b1,
                              const float* __restrict__ w2, const float* __restrict__ b2,
                              const float* __restrict__ biases) {
    int b = blockIdx.x, t = threadIdx.x;   // 256 threads
    __shared__ float sp[C_];
    __shared__ float sh[64];
    __shared__ float sl[NK];
    __shared__ float sa[NK];
    float s = 0.f;
    #pragma unroll
    for (int ch = 0; ch < 16; ++ch) s += g_part[(b * 16 + ch) * C_ + t];
    sp[t] = s * (1.0f / 3136.0f);
    __syncthreads();
    if (t < 64) {
        float acc = b1[t];
        #pragma unroll 4
        for (int c = 0; c < C_; ++c) acc += sp[c] * w1[c * 64 + t];
        sh[t] = fmaxf(acc, 0.f);
    }
    __syncthreads();
    if (t < NK) {
        float lg = b2[t];
        #pragma unroll
        for (int i = 0; i < 64; ++i) lg += sh[i] * w2[i * NK + t];
        sl[t] = lg * (1.0f / 30.0f);
    }
    __syncthreads();
    if (t == 0) {
        float mx = fmaxf(fmaxf(sl[0], sl[1]), fmaxf(sl[2], sl[3]));
        float e0 = expf(sl[0] - mx), e1 = expf(sl[1] - mx);
        float e2 = expf(sl[2] - mx), e3 = expf(sl[3] - mx);
        float inv = 1.0f / (e0 + e1 + e2 + e3);
        sa[0] = e0 * inv; sa[1] = e1 * inv; sa[2] = e2 * inv; sa[3] = e3 * inv;
        g_attn[b * NK + 0] = sa[0]; g_attn[b * NK + 1] = sa[1];
        g_attn[b * NK + 2] = sa[2]; g_attn[b * NK + 3] = sa[3];
    }
    __syncthreads();
    float bs = 0.f;
    #pragma unroll
    for (int k = 0; k < NK; ++k) bs += sa[k] * biases[k * F_ + t];
    g_beff[b * F_ + t] = bs;
}

// ============ 3) Weight transform (b-loop, kernels read once) ============
// Block: 8 f x 32 c tile. Grid (32, 8). Thread: (f = f0 + t>>5, c = c0 + t&31).
__global__ void __launch_bounds__(256)
wtrans_kernel(const float* __restrict__ kern) {
    __shared__ float sk[4][9][8][33];    // 38 KB, padded (conflict-free both phases)
    __shared__ float sa[B_][NK];
    const int f0 = blockIdx.x * 8;
    const int c0 = blockIdx.y * 32;
    const int t  = threadIdx.x;

    // load kernel taps: 4*9*8*32 = 9216 floats, 36 per thread
    #pragma unroll
    for (int p = 0; p < 36; ++p) {
        int i  = p * 256 + t;
        int fl = i & 7, cl = (i >> 3) & 31, rs = (i >> 8) % 9, k = i / 2304;
        sk[k][rs][fl][cl] =
            kern[(size_t)k * PER_B + (size_t)rs * (C_ * F_) + (size_t)(c0 + cl) * F_ + f0 + fl];
    }
    if (t < B_ * NK) sa[t >> 2][t & 3] = g_attn[t];
    __syncthreads();

    const int fl = t >> 5, cl = t & 31;
    #pragma unroll 1
    for (int b = 0; b < B_; ++b) {
        const float a0 = sa[b][0], a1 = sa[b][1], a2 = sa[b][2], a3 = sa[b][3];
        float g[3][3];
        #pragma unroll
        for (int rs = 0; rs < 9; ++rs)
            g[rs / 3][rs % 3] = a0 * sk[0][rs][fl][cl] + a1 * sk[1][rs][fl][cl]
                              + a2 * sk[2][rs][fl][cl] + a3 * sk[3][rs][fl][cl];
        float q[4][3];
        #pragma unroll
        for (int j = 0; j < 3; ++j) {
            q[0][j] = g[0][j];
            q[1][j] = 0.5f * (g[0][j] + g[1][j] + g[2][j]);
            q[2][j] = 0.5f * (g[0][j] - g[1][j] + g[2][j]);
            q[3][j] = g[2][j];
        }
        __half* Ub = g_U + ((size_t)(b * 16) * F_ + f0 + fl) * C_ + c0 + cl;
        #pragma unroll
        for (int i = 0; i < 4; ++i) {
            float u0 = q[i][0];
            float u1 = 0.5f * (q[i][0] + q[i][1] + q[i][2]);
            float u2 = 0.5f * (q[i][0] - q[i][1] + q[i][2]);
            float u3 = q[i][2];
            Ub[(size_t)(i * 4 + 0) * (F_ * C_)] = __float2half(u0);
            Ub[(size_t)(i * 4 + 1) * (F_ * C_)] = __float2half(u1);
            Ub[(size_t)(i * 4 + 2) * (F_ * C_)] = __float2half(u2);
            Ub[(size_t)(i * 4 + 3) * (F_ * C_)] = __float2half(u3);
        }
    }
}

// ============ 4) Fused Winograd GEMM + inverse transform (3-stage cp.async) ============
__device__ __forceinline__ void ldm_x4(uint32_t* r, uint32_t addr) {
    asm volatile("ldmatrix.sync.aligned.m8n8.x4.shared.b16 {%0,%1,%2,%3}, [%4];"
        : "=r"(r[0]), "=r"(r[1]), "=r"(r[2]), "=r"(r[3]) : "r"(addr));
}
__device__ __forceinline__ void mma_f16(float* d, const uint32_t* a, const uint32_t* bb) {
    asm volatile(
        "mma.sync.aligned.m16n8k16.row.col.f32.f16.f16.f32 "
        "{%0,%1,%2,%3},{%4,%5,%6,%7},{%8,%9},{%0,%1,%2,%3};"
        : "+f"(d[0]), "+f"(d[1]), "+f"(d[2]), "+f"(d[3])
        : "r"(a[0]), "r"(a[1]), "r"(a[2]), "r"(a[3]), "r"(bb[0]), "r"(bb[1]));
}
__device__ __forceinline__ void cpa16(uint32_t s, const void* g) {
    asm volatile("cp.async.ca.shared.global [%0], [%1], 16;" :: "r"(s), "l"(g) : "memory");
}

__global__ void __launch_bounds__(256, 2)
wino_gemm(float* __restrict__ out) {
    __shared__ __align__(16) __half As[3][64][PHW];   // U: [f][c]
    __shared__ __align__(16) __half Bs[3][64][PHW];   // V: [tile][c]

    const int t    = threadIdx.x;
    const int lane = t & 31;
    const int warp = t >> 5;
    const int wm   = warp >> 2;          // 0..1 : 32 f
    const int wn   = warp & 3;           // 0..3 : 16 tiles
    const int b    = blockIdx.z;
    const int f0   = blockIdx.y * 64;
    const int t0   = blockIdx.x * 64;

    const __half* Ub = g_U + (size_t)b * 16 * F_ * C_;
    const __half* Vb = g_V + (size_t)b * 16 * NTP * C_;

    const int arow = t >> 2, aseg = t & 3;

    const uint32_t aSm = (uint32_t)__cvta_generic_to_shared(&As[0][0][0]);
    const uint32_t bSm = (uint32_t)__cvta_generic_to_shared(&Bs[0][0][0]);
    const uint32_t aLm = aSm + (uint32_t)(((wm * 32 + (lane & 15)) * PHW + (lane >> 4) * 8) * 2);
    const uint32_t bLm = bSm + (uint32_t)(((wn * 16 + (lane & 7) + ((lane >> 4) & 1) * 8) * PHW
                                           + ((lane >> 3) & 1) * 8) * 2);
    const uint32_t aDst = aSm + (uint32_t)((arow * PHW + aseg * 8) * 2);
    const uint32_t bDst = bSm + (uint32_t)((arow * PHW + aseg * 8) * 2);
    const __half* gaB = Ub + (size_t)(f0 + arow) * C_ + aseg * 8;
    const __half* gbB = Vb + (size_t)(t0 + arow) * C_ + aseg * 8;

    float P[2][2][4];
    float o[4][2][2][4];
    #pragma unroll
    for (int mt = 0; mt < 2; ++mt)
        #pragma unroll
        for (int nt = 0; nt < 2; ++nt)
            #pragma unroll
            for (int r = 0; r < 4; ++r) P[mt][nt][r] = 0.f;
    #pragma unroll
    for (int ij = 0; ij < 4; ++ij)
        #pragma unroll
        for (int mt = 0; mt < 2; ++mt)
            #pragma unroll
            for (int nt = 0; nt < 2; ++nt)
                #pragma unroll
                for (int r = 0; r < 4; ++r) o[ij][mt][nt][r] = 0.f;

    // prologue: stages 0,1 <- indices 0,1
    #pragma unroll
    for (int j = 0; j < 2; ++j) {
        const int xi = j >> 3, kt = j & 7;
        cpa16(aDst + j * STGB, gaB + (size_t)xi * (F_ * C_) + kt * 32);
        cpa16(bDst + j * STGB, gbB + (size_t)xi * (NTP * C_) + kt * 32);
        asm volatile("cp.async.commit_group;" ::: "memory");
    }

    int cur = 0;
    #pragma unroll 1
    for (int it = 0; it < 128; ++it) {
        asm volatile("cp.async.wait_group 1;" ::: "memory");
        __syncthreads();

        const uint32_t so = (uint32_t)(cur * STGB);
        #pragma unroll
        for (int ks = 0; ks < 2; ++ks) {
            const uint32_t ko = (uint32_t)(ks * 32);
            uint32_t bfr[4];
            ldm_x4(bfr, bLm + so + ko);
            #pragma unroll
            for (int mt = 0; mt < 2; ++mt) {
                uint32_t afr[4];
                ldm_x4(afr, aLm + so + (uint32_t)(mt * 16 * PHW * 2) + ko);
                mma_f16(P[mt][0], afr, &bfr[0]);
                mma_f16(P[mt][1], afr, &bfr[2]);
            }
        }

        // fold xi into inverse-transform accumulators
        if ((it & 7) == 7) {
            const int xi = it >> 3;
            const int nu = xi >> 2, mu = xi & 3;
            const float a0n = (nu < 3) ? 1.f : 0.f;
            const float a1n = (nu == 0) ? 0.f : ((nu == 1) ? 1.f : -1.f);
            const float a0m = (mu < 3) ? 1.f : 0.f;
            const float a1m = (mu == 0) ? 0.f : ((mu == 1) ? 1.f : -1.f);
            const float c00 = a0n * a0m, c01 = a0n * a1m;
            const float c10 = a1n * a0m, c11 = a1n * a1m;
            #pragma unroll
            for (int mt = 0; mt < 2; ++mt)
                #pragma unroll
                for (int nt = 0; nt < 2; ++nt)
                    #pragma unroll
                    for (int r = 0; r < 4; ++r) {
                        const float p = P[mt][nt][r];
                        o[0][mt][nt][r] += c00 * p;
                        o[1][mt][nt][r] += c01 * p;
                        o[2][mt][nt][r] += c10 * p;
                        o[3][mt][nt][r] += c11 * p;
                        P[mt][nt][r] = 0.f;
                    }
        }

        // issue next stage (safe: barrier above ordered all compute(it-1))
        if (it + 2 < 128) {
            const int j  = it + 2;
            const int xi = j >> 3, kt = j & 7;
            int ns = cur + 2; if (ns >= 3) ns -= 3;
            cpa16(aDst + ns * STGB, gaB + (size_t)xi * (F_ * C_) + kt * 32);
            cpa16(bDst + ns * STGB, gbB + (size_t)xi * (NTP * C_) + kt * 32);
        }
        asm volatile("cp.async.commit_group;" ::: "memory");
        if (++cur == 3) cur = 0;
    }

    // ---- epilogue: 2x2 spatial per tile + bias ----
    float* ob = out + (size_t)b * HW * F_;
    const float* brow = g_beff + b * F_;
    #pragma unroll
    for (int mt = 0; mt < 2; ++mt) {
        #pragma unroll
        for (int rh = 0; rh < 2; ++rh) {
            const int f = f0 + wm * 32 + (lane >> 2) + mt * 16 + rh * 8;
            const float bias = brow[f];
            #pragma unroll
            for (int nt = 0; nt < 2; ++nt) {
                #pragma unroll
                for (int cx = 0; cx < 2; ++cx) {
                    const int tv = t0 + wn * 16 + nt * 8 + (lane & 3) * 2 + cx;
                    if (tv < NT) {
                        const int ti = tv / 28, tj = tv % 28;
                        const int r = rh * 2 + cx;
                        #pragma unroll
                        for (int i = 0; i < 2; ++i)
                            #pragma unroll
                            for (int j = 0; j < 2; ++j) {
                                const int h = 2 * ti + i, w = 2 * tj + j;
                                ob[(size_t)(h * 56 + w) * F_ + f] =
                                    o[i * 2 + j][mt][nt][r] + bias;
                            }
                    }
                }
            }
        }
    }
}

// ============ launch ============
extern "C" void kernel_launch(void* const* d_in, const int* in_sizes, int n_in,
                              void* d_out, int out_size) {
    const float* x       = (const float*)d_in[0];
    const float* kernels = (const float*)d_in[1];
    const float* biases  = (const float*)d_in[2];
    const float* w1      = (const float*)d_in[3];
    const float* b1      = (const float*)d_in[4];
    const float* w2      = (const float*)d_in[5];
    const float* b2      = (const float*)d_in[6];
    float* out = (float*)d_out;

    itrans_kernel<<<dim3(16, 8, B_), 256>>>(x);
    router_kernel<<<B_, 256>>>(w1, b1, w2, b2, biases);
    wtrans_kernel<<<dim3(32, 8), 256>>>(kernels);
    wino_gemm<<<dim3(13, 4, B_), 256>>>(out);
}

// round 9
// speedup vs baseline: 6.0165x; 1.0009x over previous
#include <cuda_runtime.h>
#include <cuda_fp16.h>
#include <cstdint>

#define B_  32
#define HW  3136
#define C_  256
#define F_  256
#define NK  4
#define PER_B (2304*256)
#define NT  784            // 28x28 winograd tiles per sample
#define NTP 832            // padded tiles (13 blocks of 64); pad region stays zero
#define PHW 40             // smem pitch (halves)
#define STGB (64*PHW*2)    // stage stride bytes (5120)

// ---------------- scratch ----------------
__device__ float g_part[B_ * 16 * C_];
__device__ float g_attn[B_ * NK];
__device__ float g_beff[B_ * F_];
__device__ __half g_U[(size_t)B_ * 16 * F_ * C_];        // [b][xi][f][c]
__device__ __half g_V[(size_t)B_ * 16 * NTP * C_];       // [b][xi][tile][c] (pad zero)

// ============ 1) Input transform (smem-tiled) + fused GAP partial ============
// Block: 7x7 tile patch (16x16 pixels) x 32 channels. Grid (16, 8, 32).
__global__ void __launch_bounds__(256)
itrans_kernel(const float* __restrict__ x) {
    __shared__ float sx[16 * 16 * 32];   // 32 KB
    __shared__ float red[8][32];
    const int b  = blockIdx.z;
    const int c0 = blockIdx.y * 32;
    const int pi = blockIdx.x >> 2, pj = blockIdx.x & 3;
    const int ti0 = pi * 7, tj0 = pj * 7;
    const int t = threadIdx.x;

    const float* xb = x + (size_t)b * HW * C_ + c0;
    // load 16x16 px x 32c: 2048 float4 units, 8 per thread
    #pragma unroll
    for (int p = 0; p < 8; ++p) {
        int u  = p * 256 + t;
        int px = u >> 3, cu = u & 7;
        int rp = px >> 4, cp = px & 15;
        int ih = 2 * ti0 - 1 + rp, iw = 2 * tj0 - 1 + cp;
        float4 v = make_float4(0.f, 0.f, 0.f, 0.f);
        if ((unsigned)ih < 56u && (unsigned)iw < 56u)
            v = *(const float4*)(xb + (size_t)(ih * 56 + iw) * C_ + cu * 4);
        *(float4*)(sx + px * 32 + cu * 4) = v;
    }
    __syncthreads();

    // ---- fused GAP partial over exclusive 14x14 interior ----
    {
        const int part = t >> 5, cl = t & 31;
        float ps = 0.f;
        for (int i = part; i < 196; i += 8) {
            int rp = 1 + i / 14, cp = 1 + i % 14;
            ps += sx[(rp * 16 + cp) * 32 + cl];
        }
        red[part][cl] = ps;
    }
    __syncthreads();
    if (t < 32) {
        float s = 0.f;
        #pragma unroll
        for (int r = 0; r < 8; ++r) s += red[r][t];
        g_part[(b * 16 + blockIdx.x) * C_ + c0 + t] = s;
    }

    // ---- 49 tiles x 8 c-groups = 392 transform items ----
    for (int item = t; item < 392; item += 256) {
        const int tile = item >> 3, cg = item & 7;
        const int lti = tile / 7, ltj = tile % 7;

        float4 d[4][4];
        #pragma unroll
        for (int i = 0; i < 4; ++i)
            #pragma unroll
            for (int j = 0; j < 4; ++j) {
                int px = (2 * lti + i) * 16 + (2 * ltj + j);
                d[i][j] = *(const float4*)(sx + px * 32 + cg * 4);
            }

        const int tg = (ti0 + lti) * 28 + (tj0 + ltj);
        __half* Vb = g_V + ((size_t)(b * 16) * NTP + tg) * C_ + c0 + cg * 4;
        #pragma unroll
        for (int nu = 0; nu < 4; ++nu) {
            float4 T[4];
            #pragma unroll
            for (int j = 0; j < 4; ++j) {
                T[j] = (nu == 0) ? make_float4(d[0][j].x-d[2][j].x, d[0][j].y-d[2][j].y,
                                               d[0][j].z-d[2][j].z, d[0][j].w-d[2][j].w) :
                       (nu == 1) ? make_float4(d[1][j].x+d[2][j].x, d[1][j].y+d[2][j].y,
                                               d[1][j].z+d[2][j].z, d[1][j].w+d[2][j].w) :
                       (nu == 2) ? make_float4(d[2][j].x-d[1][j].x, d[2][j].y-d[1][j].y,
                                               d[2][j].z-d[1][j].z, d[2][j].w-d[1][j].w) :
                                   make_float4(d[1][j].x-d[3][j].x, d[1][j].y-d[3][j].y,
                                               d[1][j].z-d[3][j].z, d[1][j].w-d[3][j].w);
            }
            float4 V[4];
            V[0] = make_float4(T[0].x-T[2].x, T[0].y-T[2].y, T[0].z-T[2].z, T[0].w-T[2].w);
            V[1] = make_float4(T[1].x+T[2].x, T[1].y+T[2].y, T[1].z+T[2].z, T[1].w+T[2].w);
            V[2] = make_float4(T[2].x-T[1].x, T[2].y-T[1].y, T[2].z-T[1].z, T[2].w-T[1].w);
            V[3] = make_float4(T[1].x-T[3].x, T[1].y-T[3].y, T[1].z-T[3].z, T[1].w-T[3].w);
            #pragma unroll
            for (int mu = 0; mu < 4; ++mu) {
                __half2 hlo = __floats2half2_rn(V[mu].x, V[mu].y);
                __half2 hhi = __floats2half2_rn(V[mu].z, V[mu].w);
                uint2 pk = make_uint2(*(uint32_t*)&hlo, *(uint32_t*)&hhi);
                *(uint2*)(Vb + (size_t)(nu * 4 + mu) * NTP * C_) = pk;
            }
        }
    }
}

// ============ 2) Fused: GAP final + router MLP + softmax + beff ============
__global__ void router_kernel(const float* __restrict__ w1, const float* __restrict__ b1,
                              const float* __restrict__ w2, const float* __restrict__ b2,
                              const float* __restrict__ biases) {
    int b = blockIdx.x, t = threadIdx.x;   // 256 threads
    __shared__ float sp[C_];
    __shared__ float sh[64];
    __shared__ float sl[NK];
    __shared__ float sa[NK];
    float s = 0.f;
    #pragma unroll
    for (int ch = 0; ch < 16; ++ch) s += g_part[(b * 16 + ch) * C_ + t];
    sp[t] = s * (1.0f / 3136.0f);
    __syncthreads();
    if (t < 64) {
        float acc = b1[t];
        #pragma unroll 4
        for (int c = 0; c < C_; ++c) acc += sp[c] * w1[c * 64 + t];
        sh[t] = fmaxf(acc, 0.f);
    }
    __syncthreads();
    if (t < NK) {
        float lg = b2[t];
        #pragma unroll
        for (int i = 0; i < 64; ++i) lg += sh[i] * w2[i * NK + t];
        sl[t] = lg * (1.0f / 30.0f);
    }
    __syncthreads();
    if (t == 0) {
        float mx = fmaxf(fmaxf(sl[0], sl[1]), fmaxf(sl[2], sl[3]));
        float e0 = expf(sl[0] - mx), e1 = expf(sl[1] - mx);
        float e2 = expf(sl[2] - mx), e3 = expf(sl[3] - mx);
        float inv = 1.0f / (e0 + e1 + e2 + e3);
        sa[0] = e0 * inv; sa[1] = e1 * inv; sa[2] = e2 * inv; sa[3] = e3 * inv;
        g_attn[b * NK + 0] = sa[0]; g_attn[b * NK + 1] = sa[1];
        g_attn[b * NK + 2] = sa[2]; g_attn[b * NK + 3] = sa[3];
    }
    __syncthreads();
    float bs = 0.f;
    #pragma unroll
    for (int k = 0; k < NK; ++k) bs += sa[k] * biases[k * F_ + t];
    g_beff[b * F_ + t] = bs;
}

// ============ 3) Weight transform (b-loop, kernels read once) ============
// Block: 8 f x 32 c tile. Grid (32, 8). Thread: (f = f0 + t>>5, c = c0 + t&31).
__global__ void __launch_bounds__(256)
wtrans_kernel(const float* __restrict__ kern) {
    __shared__ float sk[4][9][8][33];    // 38 KB, padded (conflict-free both phases)
    __shared__ float sa[B_][NK];
    const int f0 = blockIdx.x * 8;
    const int c0 = blockIdx.y * 32;
    const int t  = threadIdx.x;

    // load kernel taps: 4*9*8*32 = 9216 floats, 36 per thread
    #pragma unroll
    for (int p = 0; p < 36; ++p) {
        int i  = p * 256 + t;
        int fl = i & 7, cl = (i >> 3) & 31, rs = (i >> 8) % 9, k = i / 2304;
        sk[k][rs][fl][cl] =
            kern[(size_t)k * PER_B + (size_t)rs * (C_ * F_) + (size_t)(c0 + cl) * F_ + f0 + fl];
    }
    if (t < B_ * NK) sa[t >> 2][t & 3] = g_attn[t];
    __syncthreads();

    const int fl = t >> 5, cl = t & 31;
    #pragma unroll 1
    for (int b = 0; b < B_; ++b) {
        const float a0 = sa[b][0], a1 = sa[b][1], a2 = sa[b][2], a3 = sa[b][3];
        float g[3][3];
        #pragma unroll
        for (int rs = 0; rs < 9; ++rs)
            g[rs / 3][rs % 3] = a0 * sk[0][rs][fl][cl] + a1 * sk[1][rs][fl][cl]
                              + a2 * sk[2][rs][fl][cl] + a3 * sk[3][rs][fl][cl];
        float q[4][3];
        #pragma unroll
        for (int j = 0; j < 3; ++j) {
            q[0][j] = g[0][j];
            q[1][j] = 0.5f * (g[0][j] + g[1][j] + g[2][j]);
            q[2][j] = 0.5f * (g[0][j] - g[1][j] + g[2][j]);
            q[3][j] = g[2][j];
        }
        __half* Ub = g_U + ((size_t)(b * 16) * F_ + f0 + fl) * C_ + c0 + cl;
        #pragma unroll
        for (int i = 0; i < 4; ++i) {
            float u0 = q[i][0];
            float u1 = 0.5f * (q[i][0] + q[i][1] + q[i][2]);
            float u2 = 0.5f * (q[i][0] - q[i][1] + q[i][2]);
            float u3 = q[i][2];
            Ub[(size_t)(i * 4 + 0) * (F_ * C_)] = __float2half(u0);
            Ub[(size_t)(i * 4 + 1) * (F_ * C_)] = __float2half(u1);
            Ub[(size_t)(i * 4 + 2) * (F_ * C_)] = __float2half(u2);
            Ub[(size_t)(i * 4 + 3) * (F_ * C_)] = __float2half(u3);
        }
    }
}

// ============ 4) Fused Winograd GEMM + inverse transform (3-stage cp.async) ============
__device__ __forceinline__ void ldm_x4(uint32_t* r, uint32_t addr) {
    asm volatile("ldmatrix.sync.aligned.m8n8.x4.shared.b16 {%0,%1,%2,%3}, [%4];"
        : "=r"(r[0]), "=r"(r[1]), "=r"(r[2]), "=r"(r[3]) : "r"(addr));
}
__device__ __forceinline__ void mma_f16(float* d, const uint32_t* a, const uint32_t* bb) {
    asm volatile(
        "mma.sync.aligned.m16n8k16.row.col.f32.f16.f16.f32 "
        "{%0,%1,%2,%3},{%4,%5,%6,%7},{%8,%9},{%0,%1,%2,%3};"
        : "+f"(d[0]), "+f"(d[1]), "+f"(d[2]), "+f"(d[3])
        : "r"(a[0]), "r"(a[1]), "r"(a[2]), "r"(a[3]), "r"(bb[0]), "r"(bb[1]));
}
__device__ __forceinline__ void cpa16(uint32_t s, const void* g) {
    asm volatile("cp.async.ca.shared.global [%0], [%1], 16;" :: "r"(s), "l"(g) : "memory");
}

__global__ void __launch_bounds__(256, 2)
wino_gemm(float* __restrict__ out) {
    __shared__ __align__(16) __half As[3][64][PHW];   // U: [f][c]
    __shared__ __align__(16) __half Bs[3][64][PHW];   // V: [tile][c]

    const int t    = threadIdx.x;
    const int lane = t & 31;
    const int warp = t >> 5;
    const int wm   = warp >> 2;          // 0..1 : 32 f
    const int wn   = warp & 3;           // 0..3 : 16 tiles
    const int b    = blockIdx.z;
    const int f0   = blockIdx.y * 64;
    const int t0   = blockIdx.x * 64;

    const __half* Ub = g_U + (size_t)b * 16 * F_ * C_;
    const __half* Vb = g_V + (size_t)b * 16 * NTP * C_;

    const int arow = t >> 2, aseg = t & 3;

    const uint32_t aSm = (uint32_t)__cvta_generic_to_shared(&As[0][0][0]);
    const uint32_t bSm = (uint32_t)__cvta_generic_to_shared(&Bs[0][0][0]);
    const uint32_t aLm = aSm + (uint32_t)(((wm * 32 + (lane & 15)) * PHW + (lane >> 4) * 8) * 2);
    const uint32_t bLm = bSm + (uint32_t)(((wn * 16 + (lane & 7) + ((lane >> 4) & 1) * 8) * PHW
                                           + ((lane >> 3) & 1) * 8) * 2);
    const uint32_t aDst = aSm + (uint32_t)((arow * PHW + aseg * 8) * 2);
    const uint32_t bDst = bSm + (uint32_t)((arow * PHW + aseg * 8) * 2);
    const __half* gaB = Ub + (size_t)(f0 + arow) * C_ + aseg * 8;
    const __half* gbB = Vb + (size_t)(t0 + arow) * C_ + aseg * 8;

    float P[2][2][4];
    float o[4][2][2][4];
    #pragma unroll
    for (int mt = 0; mt < 2; ++mt)
        #pragma unroll
        for (int nt = 0; nt < 2; ++nt)
            #pragma unroll
            for (int r = 0; r < 4; ++r) P[mt][nt][r] = 0.f;
    #pragma unroll
    for (int ij = 0; ij < 4; ++ij)
        #pragma unroll
        for (int mt = 0; mt < 2; ++mt)
            #pragma unroll
            for (int nt = 0; nt < 2; ++nt)
                #pragma unroll
                for (int r = 0; r < 4; ++r) o[ij][mt][nt][r] = 0.f;

    // prologue: stages 0,1 <- indices 0,1
    #pragma unroll
    for (int j = 0; j < 2; ++j) {
        const int xi = j >> 3, kt = j & 7;
        cpa16(aDst + j * STGB, gaB + (size_t)xi * (F_ * C_) + kt * 32);
        cpa16(bDst + j * STGB, gbB + (size_t)xi * (NTP * C_) + kt * 32);
        asm volatile("cp.async.commit_group;" ::: "memory");
    }

    int cur = 0;
    #pragma unroll 1
    for (int it = 0; it < 128; ++it) {
        asm volatile("cp.async.wait_group 1;" ::: "memory");
        __syncthreads();

        const uint32_t so = (uint32_t)(cur * STGB);
        #pragma unroll
        for (int ks = 0; ks < 2; ++ks) {
            const uint32_t ko = (uint32_t)(ks * 32);
            uint32_t bfr[4];
            ldm_x4(bfr, bLm + so + ko);
            #pragma unroll
            for (int mt = 0; mt < 2; ++mt) {
                uint32_t afr[4];
                ldm_x4(afr, aLm + so + (uint32_t)(mt * 16 * PHW * 2) + ko);
                mma_f16(P[mt][0], afr, &bfr[0]);
                mma_f16(P[mt][1], afr, &bfr[2]);
            }
        }

        // fold xi into inverse-transform accumulators
        if ((it & 7) == 7) {
            const int xi = it >> 3;
            const int nu = xi >> 2, mu = xi & 3;
            const float a0n = (nu < 3) ? 1.f : 0.f;
            const float a1n = (nu == 0) ? 0.f : ((nu == 1) ? 1.f : -1.f);
            const float a0m = (mu < 3) ? 1.f : 0.f;
            const float a1m = (mu == 0) ? 0.f : ((mu == 1) ? 1.f : -1.f);
            const float c00 = a0n * a0m, c01 = a0n * a1m;
            const float c10 = a1n * a0m, c11 = a1n * a1m;
            #pragma unroll
            for (int mt = 0; mt < 2; ++mt)
                #pragma unroll
                for (int nt = 0; nt < 2; ++nt)
                    #pragma unroll
                    for (int r = 0; r < 4; ++r) {
                        const float p = P[mt][nt][r];
                        o[0][mt][nt][r] += c00 * p;
                        o[1][mt][nt][r] += c01 * p;
                        o[2][mt][nt][r] += c10 * p;
                        o[3][mt][nt][r] += c11 * p;
                        P[mt][nt][r] = 0.f;
                    }
        }

        // issue next stage (safe: barrier above ordered all compute(it-1))
        if (it + 2 < 128) {
            const int j  = it + 2;
            const int xi = j >> 3, kt = j & 7;
            int ns = cur + 2; if (ns >= 3) ns -= 3;
            cpa16(aDst + ns * STGB, gaB + (size_t)xi * (F_ * C_) + kt * 32);
            cpa16(bDst + ns * STGB, gbB + (size_t)xi * (NTP * C_) + kt * 32);
        }
        asm volatile("cp.async.commit_group;" ::: "memory");
        if (++cur == 3) cur = 0;
    }

    // ---- epilogue: 2x2 spatial per tile + bias ----
    float* ob = out + (size_t)b * HW * F_;
    const float* brow = g_beff + b * F_;
    #pragma unroll
    for (int mt = 0; mt < 2; ++mt) {
        #pragma unroll
        for (int rh = 0; rh < 2; ++rh) {
            const int f = f0 + wm * 32 + (lane >> 2) + mt * 16 + rh * 8;
            const float bias = brow[f];
            #pragma unroll
            for (int nt = 0; nt < 2; ++nt) {
                #pragma unroll
                for (int cx = 0; cx < 2; ++cx) {
                    const int tv = t0 + wn * 16 + nt * 8 + (lane & 3) * 2 + cx;
                    if (tv < NT) {
                        const int ti = tv / 28, tj = tv % 28;
                        const int r = rh * 2 + cx;
                        #pragma unroll
                        for (int i = 0; i < 2; ++i)
                            #pragma unroll
                            for (int j = 0; j < 2; ++j) {
                                const int h = 2 * ti + i, w = 2 * tj + j;
                                ob[(size_t)(h * 56 + w) * F_ + f] =
                                    o[i * 2 + j][mt][nt][r] + bias;
                            }
                    }
                }
            }
        }
    }
}

// ============ launch ============
extern "C" void kernel_launch(void* const* d_in, const int* in_sizes, int n_in,
                              void* d_out, int out_size) {
    const float* x       = (const float*)d_in[0];
    const float* kernels = (const float*)d_in[1];
    const float* biases  = (const float*)d_in[2];
    const float* w1      = (const float*)d_in[3];
    const float* b1      = (const float*)d_in[4];
    const float* w2      = (const float*)d_in[5];
    const float* b2      = (const float*)d_in[6];
    float* out = (float*)d_out;

    itrans_kernel<<<dim3(16, 8, B_), 256>>>(x);
    router_kernel<<<B_, 256>>>(w1, b1, w2, b2, biases);
    wtrans_kernel<<<dim3(32, 8), 256>>>(kernels);
    wino_gemm<<<dim3(13, 4, B_), 256>>>(out);
}